// round 1
// baseline (speedup 1.0000x reference)
#include <cuda_runtime.h>
#include <math_constants.h>

// FourierConv2D: out = crop(Re(IFFT2(FFT2(pad(im)) * W))) + bias
// Implemented as dense DFT matmuls (511 = 7*73 is hostile to radix FFT, and
// cuFFT plan creation allocates -> banned). All scratch in __device__ globals.

#define NF 511            // FFT size
#define HH 256            // image H=W
#define NN2 (NF*NF)       // 261121
#define BATCH_IN 16       // B*CIN
#define BATCH_OUT 32      // B*COUT
#define CROP0 127         // first kept output row/col

// ---- scratch (device globals; no allocation APIs allowed) ----
__device__ float g_Tr[NN2];               // twiddle real:  cos(-2pi*a*b/511)
__device__ float g_Ti[NN2];               // twiddle imag:  sin(-2pi*a*b/511)
__device__ float g_T1r[BATCH_IN * NF * HH];
__device__ float g_T1i[BATCH_IN * NF * HH];
__device__ float g_Fr [BATCH_IN * NN2];
__device__ float g_Fi [BATCH_IN * NN2];
__device__ float g_Gr [BATCH_OUT * NN2];
__device__ float g_Gi [BATCH_OUT * NN2];
__device__ float g_T2r[BATCH_OUT * HH * NF];
__device__ float g_T2i[BATCH_OUT * HH * NF];

// ---------------------------------------------------------------------------
// Twiddle table: T[a][b] = exp(-2*pi*i*a*b/511)
__global__ void __launch_bounds__(256) k_twiddle() {
    int p = blockIdx.x * 256 + threadIdx.x;
    if (p >= NN2) return;
    int a = p / NF, b = p - a * NF;
    int r = (a * b) % NF;                       // < 261121 fits int
    float ang = (-2.0f * CUDART_PI_F / (float)NF) * (float)r;
    float s, c;
    sincosf(ang, &s, &c);
    g_Tr[p] = c;
    g_Ti[p] = s;
}

// ---------------------------------------------------------------------------
// G1: T1[bc][k1][n2] = sum_{n1<256} T[k1][n1] * x[bc][n1][n2]
//     complex-A (511x256, lda=511) x real-B (256x256) -> complex C (511x256)
__global__ void __launch_bounds__(256) k_fwd_cols(const float* __restrict__ x) {
    const int batch = blockIdx.z;
    const int m0 = blockIdx.y * 64;       // k1
    const int n0 = blockIdx.x * 64;       // n2
    const float* B = x + batch * (HH * HH);
    float* Cr = g_T1r + batch * (NF * HH);
    float* Ci = g_T1i + batch * (NF * HH);

    __shared__ float sAr[16][64], sAi[16][64], sB[16][64];
    const int t = threadIdx.x;
    const int tx = t & 15, ty = t >> 4;
    float cr[4][4] = {}, ci[4][4] = {};

    for (int k0 = 0; k0 < HH; k0 += 16) {
        // A tile: [m][k] row-major, lda = NF (cols 0..255 used)
        #pragma unroll
        for (int i = 0; i < 4; i++) {
            int ml = (t >> 4) + i * 16;
            int kl = t & 15;
            int gm = m0 + ml;
            float vr = 0.f, vi = 0.f;
            if (gm < NF) {
                int idx = gm * NF + k0 + kl;
                vr = g_Tr[idx]; vi = g_Ti[idx];
            }
            sAr[kl][ml] = vr; sAi[kl][ml] = vi;
        }
        // B tile: [k][n] row-major, ldb = 256, no guards (exact)
        #pragma unroll
        for (int i = 0; i < 4; i++) {
            int kl = (t >> 6) + i * 4;
            int nl = t & 63;
            sB[kl][nl] = B[(k0 + kl) * HH + n0 + nl];
        }
        __syncthreads();
        #pragma unroll
        for (int k = 0; k < 16; k++) {
            float ar[4], ai[4], bb[4];
            #pragma unroll
            for (int i = 0; i < 4; i++) { ar[i] = sAr[k][ty*4+i]; ai[i] = sAi[k][ty*4+i]; }
            #pragma unroll
            for (int j = 0; j < 4; j++) bb[j] = sB[k][tx*4+j];
            #pragma unroll
            for (int i = 0; i < 4; i++)
                #pragma unroll
                for (int j = 0; j < 4; j++) {
                    cr[i][j] += ar[i] * bb[j];
                    ci[i][j] += ai[i] * bb[j];
                }
        }
        __syncthreads();
    }
    #pragma unroll
    for (int i = 0; i < 4; i++) {
        int gm = m0 + ty * 4 + i;
        if (gm >= NF) continue;
        #pragma unroll
        for (int j = 0; j < 4; j++) {
            int gn = n0 + tx * 4 + j;
            Cr[gm * HH + gn] = cr[i][j];
            Ci[gm * HH + gn] = ci[i][j];
        }
    }
}

// ---------------------------------------------------------------------------
// G2: F[bc][k1][k2] = sum_{n2<256} T1[k1][n2] * T[k2][n2]   (complex NT)
__global__ void __launch_bounds__(256) k_fwd_rows() {
    const int batch = blockIdx.z;
    const int m0 = blockIdx.y * 64;   // k1
    const int n0 = blockIdx.x * 64;   // k2
    const float* Ar = g_T1r + batch * (NF * HH);
    const float* Ai = g_T1i + batch * (NF * HH);
    float* Cr = g_Fr + batch * NN2;
    float* Ci = g_Fi + batch * NN2;

    __shared__ float sAr[16][64], sAi[16][64], sBr[16][64], sBi[16][64];
    const int t = threadIdx.x;
    const int tx = t & 15, ty = t >> 4;
    float cr[4][4] = {}, ci[4][4] = {};

    for (int k0 = 0; k0 < HH; k0 += 16) {
        #pragma unroll
        for (int i = 0; i < 4; i++) {
            int ml = (t >> 4) + i * 16;
            int kl = t & 15;
            int gm = m0 + ml;
            float vr = 0.f, vi = 0.f;
            if (gm < NF) { vr = Ar[gm * HH + k0 + kl]; vi = Ai[gm * HH + k0 + kl]; }
            sAr[kl][ml] = vr; sAi[kl][ml] = vi;
        }
        #pragma unroll
        for (int i = 0; i < 4; i++) {
            int nl = (t >> 4) + i * 16;
            int kl = t & 15;
            int gn = n0 + nl;
            float vr = 0.f, vi = 0.f;
            if (gn < NF) {
                int idx = gn * NF + k0 + kl;   // T rows k2, cols n2<256
                vr = g_Tr[idx]; vi = g_Ti[idx];
            }
            sBr[kl][nl] = vr; sBi[kl][nl] = vi;
        }
        __syncthreads();
        #pragma unroll
        for (int k = 0; k < 16; k++) {
            float ar[4], ai[4], br[4], bi[4];
            #pragma unroll
            for (int i = 0; i < 4; i++) { ar[i] = sAr[k][ty*4+i]; ai[i] = sAi[k][ty*4+i]; }
            #pragma unroll
            for (int j = 0; j < 4; j++) { br[j] = sBr[k][tx*4+j]; bi[j] = sBi[k][tx*4+j]; }
            #pragma unroll
            for (int i = 0; i < 4; i++)
                #pragma unroll
                for (int j = 0; j < 4; j++) {
                    cr[i][j] += ar[i] * br[j] - ai[i] * bi[j];
                    ci[i][j] += ar[i] * bi[j] + ai[i] * br[j];
                }
        }
        __syncthreads();
    }
    #pragma unroll
    for (int i = 0; i < 4; i++) {
        int gm = m0 + ty * 4 + i;
        if (gm >= NF) continue;
        #pragma unroll
        for (int j = 0; j < 4; j++) {
            int gn = n0 + tx * 4 + j;
            if (gn >= NF) continue;
            Cr[gm * NF + gn] = cr[i][j];
            Ci[gm * NF + gn] = ci[i][j];
        }
    }
}

// ---------------------------------------------------------------------------
// Einsum over CIN:  G[b,o][p] = sum_c F[b,c][p] * (wr + i*wi)[o,c][p]
__global__ void __launch_bounds__(256) k_einsum(const float* __restrict__ w) {
    int p = blockIdx.x * 256 + threadIdx.x;
    if (p >= NN2) return;
    float fr[16], fi[16];
    #pragma unroll
    for (int bc = 0; bc < 16; bc++) {
        fr[bc] = g_Fr[bc * NN2 + p];
        fi[bc] = g_Fi[bc * NN2 + p];
    }
    #pragma unroll
    for (int o = 0; o < 8; o++) {
        float wr[4], wi[4];
        #pragma unroll
        for (int c = 0; c < 4; c++) {
            int wi_idx = ((o * 4 + c) * NN2 + p) * 2;
            wr[c] = w[wi_idx];
            wi[c] = w[wi_idx + 1];
        }
        #pragma unroll
        for (int b = 0; b < 4; b++) {
            float ar = 0.f, ai = 0.f;
            #pragma unroll
            for (int c = 0; c < 4; c++) {
                float xr = fr[b * 4 + c], xi = fi[b * 4 + c];
                ar += xr * wr[c] - xi * wi[c];
                ai += xr * wi[c] + xi * wr[c];
            }
            g_Gr[(b * 8 + o) * NN2 + p] = ar;
            g_Gi[(b * 8 + o) * NN2 + p] = ai;
        }
    }
}

// ---------------------------------------------------------------------------
// G3: T2[bo][n1][k2] = sum_k1 conj(T[127+n1][k1]) * G[bo][k1][k2]  (NN, conj-A)
__global__ void __launch_bounds__(256) k_inv_cols() {
    const int batch = blockIdx.z;
    const int m0 = blockIdx.y * 64;     // n1 (M=256)
    const int n0 = blockIdx.x * 64;     // k2 (N=511)
    const float* Br = g_Gr + batch * NN2;
    const float* Bi = g_Gi + batch * NN2;
    float* Cr = g_T2r + batch * (HH * NF);
    float* Ci = g_T2i + batch * (HH * NF);

    __shared__ float sAr[16][64], sAi[16][64], sBr[16][64], sBi[16][64];
    const int t = threadIdx.x;
    const int tx = t & 15, ty = t >> 4;
    float cr[4][4] = {}, ci[4][4] = {};

    for (int k0 = 0; k0 < NF; k0 += 16) {
        #pragma unroll
        for (int i = 0; i < 4; i++) {
            int ml = (t >> 4) + i * 16;    // m local, always < 256 region
            int kl = t & 15;
            int gk = k0 + kl;
            float vr = 0.f, vi = 0.f;
            if (gk < NF) {
                int idx = (CROP0 + m0 + ml) * NF + gk;
                vr = g_Tr[idx]; vi = g_Ti[idx];
            }
            sAr[kl][ml] = vr; sAi[kl][ml] = vi;
        }
        #pragma unroll
        for (int i = 0; i < 4; i++) {
            int kl = (t >> 6) + i * 4;
            int nl = t & 63;
            int gk = k0 + kl, gn = n0 + nl;
            float vr = 0.f, vi = 0.f;
            if (gk < NF && gn < NF) { vr = Br[gk * NF + gn]; vi = Bi[gk * NF + gn]; }
            sBr[kl][nl] = vr; sBi[kl][nl] = vi;
        }
        __syncthreads();
        #pragma unroll
        for (int k = 0; k < 16; k++) {
            float ar[4], ai[4], br[4], bi[4];
            #pragma unroll
            for (int i = 0; i < 4; i++) { ar[i] = sAr[k][ty*4+i]; ai[i] = sAi[k][ty*4+i]; }
            #pragma unroll
            for (int j = 0; j < 4; j++) { br[j] = sBr[k][tx*4+j]; bi[j] = sBi[k][tx*4+j]; }
            // conj(A)*B: re = ar*br + ai*bi ; im = ar*bi - ai*br
            #pragma unroll
            for (int i = 0; i < 4; i++)
                #pragma unroll
                for (int j = 0; j < 4; j++) {
                    cr[i][j] += ar[i] * br[j] + ai[i] * bi[j];
                    ci[i][j] += ar[i] * bi[j] - ai[i] * br[j];
                }
        }
        __syncthreads();
    }
    #pragma unroll
    for (int i = 0; i < 4; i++) {
        int gm = m0 + ty * 4 + i;     // < 256 always
        #pragma unroll
        for (int j = 0; j < 4; j++) {
            int gn = n0 + tx * 4 + j;
            if (gn >= NF) continue;
            Cr[gm * NF + gn] = cr[i][j];
            Ci[gm * NF + gn] = ci[i][j];
        }
    }
}

// ---------------------------------------------------------------------------
// G4: out[bo][n1][n2] = (1/511^2)*sum_k2 (T2r*Tr[127+n2][k2] + T2i*Ti[127+n2][k2]) + bias[o]
//     (real part of T2 * conj(T)^T), complex NT with real output
__global__ void __launch_bounds__(256) k_inv_rows(const float* __restrict__ bias,
                                                  float* __restrict__ out) {
    const int batch = blockIdx.z;           // bo = b*8 + o
    const int m0 = blockIdx.y * 64;         // n1
    const int n0 = blockIdx.x * 64;         // n2
    const float* Ar = g_T2r + batch * (HH * NF);
    const float* Ai = g_T2i + batch * (HH * NF);
    float* C = out + batch * (HH * HH);
    const float scale = 1.0f / ((float)NF * (float)NF);
    const float bv = bias[batch & 7];

    __shared__ float sAr[16][64], sAi[16][64], sBr[16][64], sBi[16][64];
    const int t = threadIdx.x;
    const int tx = t & 15, ty = t >> 4;
    float cc[4][4] = {};

    for (int k0 = 0; k0 < NF; k0 += 16) {
        #pragma unroll
        for (int i = 0; i < 4; i++) {
            int ml = (t >> 4) + i * 16;
            int kl = t & 15;
            int gk = k0 + kl;
            float vr = 0.f, vi = 0.f;
            if (gk < NF) { vr = Ar[(m0 + ml) * NF + gk]; vi = Ai[(m0 + ml) * NF + gk]; }
            sAr[kl][ml] = vr; sAi[kl][ml] = vi;
        }
        #pragma unroll
        for (int i = 0; i < 4; i++) {
            int nl = (t >> 4) + i * 16;
            int kl = t & 15;
            int gk = k0 + kl;
            float vr = 0.f, vi = 0.f;
            if (gk < NF) {
                int idx = (CROP0 + n0 + nl) * NF + gk;
                vr = g_Tr[idx]; vi = g_Ti[idx];
            }
            sBr[kl][nl] = vr; sBi[kl][nl] = vi;
        }
        __syncthreads();
        #pragma unroll
        for (int k = 0; k < 16; k++) {
            float ar[4], ai[4], br[4], bi[4];
            #pragma unroll
            for (int i = 0; i < 4; i++) { ar[i] = sAr[k][ty*4+i]; ai[i] = sAi[k][ty*4+i]; }
            #pragma unroll
            for (int j = 0; j < 4; j++) { br[j] = sBr[k][tx*4+j]; bi[j] = sBi[k][tx*4+j]; }
            #pragma unroll
            for (int i = 0; i < 4; i++)
                #pragma unroll
                for (int j = 0; j < 4; j++)
                    cc[i][j] += ar[i] * br[j] + ai[i] * bi[j];
        }
        __syncthreads();
    }
    #pragma unroll
    for (int i = 0; i < 4; i++) {
        int gm = m0 + ty * 4 + i;
        #pragma unroll
        for (int j = 0; j < 4; j++) {
            int gn = n0 + tx * 4 + j;
            C[gm * HH + gn] = cc[i][j] * scale + bv;
        }
    }
}

// ---------------------------------------------------------------------------
extern "C" void kernel_launch(void* const* d_in, const int* in_sizes, int n_in,
                              void* d_out, int out_size) {
    const float* im   = (const float*)d_in[0];   // (4,4,256,256)
    const float* wgt  = (const float*)d_in[1];   // (8,4,511,511,2)
    const float* bias = (const float*)d_in[2];   // (8,1,1)
    float* out = (float*)d_out;                  // (4,8,256,256)

    k_twiddle<<<(NN2 + 255) / 256, 256>>>();
    k_fwd_cols<<<dim3(4, 8, BATCH_IN),  256>>>(im);
    k_fwd_rows<<<dim3(8, 8, BATCH_IN),  256>>>();
    k_einsum  <<<(NN2 + 255) / 256, 256>>>(wgt);
    k_inv_cols<<<dim3(8, 4, BATCH_OUT), 256>>>();
    k_inv_rows<<<dim3(4, 4, BATCH_OUT), 256>>>(bias, out);
}

// round 3
// speedup vs baseline: 1.2734x; 1.2734x over previous
#include <cuda_runtime.h>
#include <math_constants.h>

// FourierConv2D via dense DFT matmuls, fp32 with packed f32x2 FMAs.
// Hermitian symmetry: forward transform computed only for rows 0..255.
// All 511-wide arrays padded to stride 512 with zeroed row/col 511 so the
// GEMM kernels run guard-free with vectorized loads.

#define NF 511
#define LD 512
#define HH 256
#define CROP0 127
#define NN2 (NF*NF)

typedef unsigned long long u64;

// ---- scratch (device globals; zero-initialized at module load) ----
__device__ float g_Tr[LD*LD],      g_Ti[LD*LD];       // twiddle, padded, row/col 511 = 0
__device__ float g_T1r[16*HH*HH],  g_T1i[16*HH*HH];   // [bc][k1<256][n2<256]
__device__ float g_Fr[16*HH*LD],   g_Fi[16*HH*LD];    // [bc][k1<256][k2], col 511 = 0
__device__ float g_Gr[32*LD*LD],   g_Gi[32*LD*LD];    // [bo][k1][k2], row/col 511 = 0
__device__ float g_T2r[32*HH*LD],  g_T2i[32*HH*LD];   // [bo][n1<256][k2], col 511 = 0

// ---- f32x2 helpers (packed pair carried in a 64-bit integer register) ----
__device__ __forceinline__ void fma2(u64 &d, u64 a, u64 b) {
    asm("fma.rn.f32x2 %0, %1, %2, %0;" : "+l"(d) : "l"(a), "l"(b));
}
__device__ __forceinline__ u64 pack2(float lo, float hi) {
    u64 r; asm("mov.b64 %0, {%1,%2};" : "=l"(r) : "f"(lo), "f"(hi)); return r;
}
__device__ __forceinline__ void unpack2(u64 v, float &lo, float &hi) {
    asm("mov.b64 {%0,%1}, %2;" : "=f"(lo), "=f"(hi) : "l"(v));
}

// ---------------------------------------------------------------------------
// Twiddle: T[a][b] = exp(-2*pi*i*a*b/511), padded row/col 511 zeroed.
__global__ void __launch_bounds__(256) k_twiddle() {
    int p = blockIdx.x * 256 + threadIdx.x;          // covers 512*512
    int a = p >> 9, b = p & 511;
    float cr = 0.f, ci = 0.f;
    if (a < NF && b < NF) {
        int r = (a * b) % NF;
        float ang = (-2.0f * CUDART_PI_F / (float)NF) * (float)r;
        sincosf(ang, &ci, &cr);
    }
    g_Tr[p] = cr;
    g_Ti[p] = ci;
}

// ---------------------------------------------------------------------------
// G1: T1[k1][n2] = sum_{n1<256} T[k1][n1] * x[n1][n2]    (cplx A, real B)
// M=256 (k1), N=256 (n2), K=256. grid (4, 2, 16)
__global__ void __launch_bounds__(256, 2) k_fwd_cols(const float* __restrict__ x) {
    const int batch = blockIdx.z;
    const int m0 = blockIdx.y * 128;
    const int n0 = blockIdx.x * 64;
    const float* __restrict__ B = x + batch * (HH * HH);
    float* Cr = g_T1r + batch * (HH * HH);
    float* Ci = g_T1i + batch * (HH * HH);

    __shared__ __align__(16) float sAr[8][128], sAi[8][128], sB[8][128];

    const int t = threadIdx.x;
    const int tx = t & 15, ty = t >> 4;
    const int arow = t >> 1, akp = (t & 1) * 4;      // A: [m][k], 128x8
    const int bk = t >> 4,  bn4 = (t & 15) * 4;      // B (NN): [k][n], 8x64 (t<128)

    u64 cr[4][4], ci[4][4];
    #pragma unroll
    for (int i = 0; i < 4; i++)
        #pragma unroll
        for (int j = 0; j < 4; j++) { cr[i][j] = 0ull; ci[i][j] = 0ull; }

    float4 va_r, va_i, vb;
    va_r = *(const float4*)&g_Tr[(m0 + arow) * LD + akp];
    va_i = *(const float4*)&g_Ti[(m0 + arow) * LD + akp];
    if (t < 128) vb = *(const float4*)&B[bk * HH + n0 + bn4];

    const int NCH = HH / 8;
    for (int c = 0; c < NCH; c++) {
        __syncthreads();
        sAr[akp+0][arow] = va_r.x; sAr[akp+1][arow] = va_r.y;
        sAr[akp+2][arow] = va_r.z; sAr[akp+3][arow] = va_r.w;
        sAi[akp+0][arow] = va_i.x; sAi[akp+1][arow] = va_i.y;
        sAi[akp+2][arow] = va_i.z; sAi[akp+3][arow] = va_i.w;
        if (t < 128) {
            *(u64*)&sB[bk][2*(bn4+0)] = pack2(vb.x, vb.x);
            *(u64*)&sB[bk][2*(bn4+1)] = pack2(vb.y, vb.y);
            *(u64*)&sB[bk][2*(bn4+2)] = pack2(vb.z, vb.z);
            *(u64*)&sB[bk][2*(bn4+3)] = pack2(vb.w, vb.w);
        }
        __syncthreads();
        if (c + 1 < NCH) {
            int k0 = (c + 1) * 8;
            va_r = *(const float4*)&g_Tr[(m0 + arow) * LD + k0 + akp];
            va_i = *(const float4*)&g_Ti[(m0 + arow) * LD + k0 + akp];
            if (t < 128) vb = *(const float4*)&B[(k0 + bk) * HH + n0 + bn4];
        }
        #pragma unroll
        for (int k = 0; k < 8; k++) {
            ulonglong2 A0 = *(const ulonglong2*)&sAr[k][ty*8];
            ulonglong2 A1 = *(const ulonglong2*)&sAr[k][ty*8+4];
            ulonglong2 E0 = *(const ulonglong2*)&sAi[k][ty*8];
            ulonglong2 E1 = *(const ulonglong2*)&sAi[k][ty*8+4];
            u64 ar[4] = {A0.x, A0.y, A1.x, A1.y};
            u64 ai_[4] = {E0.x, E0.y, E1.x, E1.y};
            #pragma unroll
            for (int j = 0; j < 4; j++) {
                u64 bb = *(const u64*)&sB[k][2*(tx*4+j)];
                #pragma unroll
                for (int i2 = 0; i2 < 4; i2++) {
                    fma2(cr[i2][j], ar[i2], bb);
                    fma2(ci[i2][j], ai_[i2], bb);
                }
            }
        }
    }
    #pragma unroll
    for (int i2 = 0; i2 < 4; i2++) {
        float lo[4], hi[4];
        int row = m0 + ty * 8 + 2 * i2;
        #pragma unroll
        for (int j = 0; j < 4; j++) unpack2(cr[i2][j], lo[j], hi[j]);
        *(float4*)&Cr[row * HH + n0 + tx*4]     = make_float4(lo[0],lo[1],lo[2],lo[3]);
        *(float4*)&Cr[(row+1) * HH + n0 + tx*4] = make_float4(hi[0],hi[1],hi[2],hi[3]);
        #pragma unroll
        for (int j = 0; j < 4; j++) unpack2(ci[i2][j], lo[j], hi[j]);
        *(float4*)&Ci[row * HH + n0 + tx*4]     = make_float4(lo[0],lo[1],lo[2],lo[3]);
        *(float4*)&Ci[(row+1) * HH + n0 + tx*4] = make_float4(hi[0],hi[1],hi[2],hi[3]);
    }
}

// ---------------------------------------------------------------------------
// G2: F[k1][k2] = sum_{n2<256} T1[k1][n2] * T[k2][n2]   (cplx NT)
// M=256, N=512 (row 511 of T is zero -> F col 511 = 0), K=256. grid (8, 2, 16)
__global__ void __launch_bounds__(256, 2) k_fwd_rows() {
    const int batch = blockIdx.z;
    const int m0 = blockIdx.y * 128;
    const int n0 = blockIdx.x * 64;
    const float* __restrict__ Ar = g_T1r + batch * (HH * HH);
    const float* __restrict__ Ai = g_T1i + batch * (HH * HH);
    float* Cr = g_Fr + batch * (HH * LD);
    float* Ci = g_Fi + batch * (HH * LD);

    __shared__ __align__(16) float sAr[8][128], sAi[8][128];
    __shared__ __align__(16) float sBrr[8][128], sBii[8][128], sBnn[8][128];

    const int t = threadIdx.x;
    const int tx = t & 15, ty = t >> 4;
    const int arow = t >> 1, akp = (t & 1) * 4;
    const int bn = t >> 1,  bkp = (t & 1) * 4;       // B (NT): [n][k], 64x8 (t<128)

    u64 cr[4][4], ci[4][4];
    #pragma unroll
    for (int i = 0; i < 4; i++)
        #pragma unroll
        for (int j = 0; j < 4; j++) { cr[i][j] = 0ull; ci[i][j] = 0ull; }

    float4 va_r, va_i, vb_r, vb_i;
    va_r = *(const float4*)&Ar[(m0 + arow) * HH + akp];
    va_i = *(const float4*)&Ai[(m0 + arow) * HH + akp];
    if (t < 128) {
        vb_r = *(const float4*)&g_Tr[(n0 + bn) * LD + bkp];
        vb_i = *(const float4*)&g_Ti[(n0 + bn) * LD + bkp];
    }
    const int NCH = HH / 8;
    for (int c = 0; c < NCH; c++) {
        __syncthreads();
        sAr[akp+0][arow] = va_r.x; sAr[akp+1][arow] = va_r.y;
        sAr[akp+2][arow] = va_r.z; sAr[akp+3][arow] = va_r.w;
        sAi[akp+0][arow] = va_i.x; sAi[akp+1][arow] = va_i.y;
        sAi[akp+2][arow] = va_i.z; sAi[akp+3][arow] = va_i.w;
        if (t < 128) {
            *(u64*)&sBrr[bkp+0][2*bn] = pack2(vb_r.x, vb_r.x);
            *(u64*)&sBrr[bkp+1][2*bn] = pack2(vb_r.y, vb_r.y);
            *(u64*)&sBrr[bkp+2][2*bn] = pack2(vb_r.z, vb_r.z);
            *(u64*)&sBrr[bkp+3][2*bn] = pack2(vb_r.w, vb_r.w);
            *(u64*)&sBii[bkp+0][2*bn] = pack2(vb_i.x, vb_i.x);
            *(u64*)&sBii[bkp+1][2*bn] = pack2(vb_i.y, vb_i.y);
            *(u64*)&sBii[bkp+2][2*bn] = pack2(vb_i.z, vb_i.z);
            *(u64*)&sBii[bkp+3][2*bn] = pack2(vb_i.w, vb_i.w);
            *(u64*)&sBnn[bkp+0][2*bn] = pack2(-vb_i.x, -vb_i.x);
            *(u64*)&sBnn[bkp+1][2*bn] = pack2(-vb_i.y, -vb_i.y);
            *(u64*)&sBnn[bkp+2][2*bn] = pack2(-vb_i.z, -vb_i.z);
            *(u64*)&sBnn[bkp+3][2*bn] = pack2(-vb_i.w, -vb_i.w);
        }
        __syncthreads();
        if (c + 1 < NCH) {
            int k0 = (c + 1) * 8;
            va_r = *(const float4*)&Ar[(m0 + arow) * HH + k0 + akp];
            va_i = *(const float4*)&Ai[(m0 + arow) * HH + k0 + akp];
            if (t < 128) {
                vb_r = *(const float4*)&g_Tr[(n0 + bn) * LD + k0 + bkp];
                vb_i = *(const float4*)&g_Ti[(n0 + bn) * LD + k0 + bkp];
            }
        }
        #pragma unroll
        for (int k = 0; k < 8; k++) {
            ulonglong2 A0 = *(const ulonglong2*)&sAr[k][ty*8];
            ulonglong2 A1 = *(const ulonglong2*)&sAr[k][ty*8+4];
            ulonglong2 E0 = *(const ulonglong2*)&sAi[k][ty*8];
            ulonglong2 E1 = *(const ulonglong2*)&sAi[k][ty*8+4];
            u64 ar[4] = {A0.x, A0.y, A1.x, A1.y};
            u64 ai_[4] = {E0.x, E0.y, E1.x, E1.y};
            #pragma unroll
            for (int j = 0; j < 4; j++) {
                int jj = 2 * (tx*4 + j);
                u64 brr = *(const u64*)&sBrr[k][jj];
                u64 bii = *(const u64*)&sBii[k][jj];
                u64 bnn = *(const u64*)&sBnn[k][jj];
                #pragma unroll
                for (int i2 = 0; i2 < 4; i2++) {
                    fma2(cr[i2][j], ar[i2], brr);
                    fma2(cr[i2][j], ai_[i2], bnn);
                    fma2(ci[i2][j], ar[i2], bii);
                    fma2(ci[i2][j], ai_[i2], brr);
                }
            }
        }
    }
    #pragma unroll
    for (int i2 = 0; i2 < 4; i2++) {
        float lo[4], hi[4];
        int row = m0 + ty * 8 + 2 * i2;
        #pragma unroll
        for (int j = 0; j < 4; j++) unpack2(cr[i2][j], lo[j], hi[j]);
        *(float4*)&Cr[row * LD + n0 + tx*4]     = make_float4(lo[0],lo[1],lo[2],lo[3]);
        *(float4*)&Cr[(row+1) * LD + n0 + tx*4] = make_float4(hi[0],hi[1],hi[2],hi[3]);
        #pragma unroll
        for (int j = 0; j < 4; j++) unpack2(ci[i2][j], lo[j], hi[j]);
        *(float4*)&Ci[row * LD + n0 + tx*4]     = make_float4(lo[0],lo[1],lo[2],lo[3]);
        *(float4*)&Ci[(row+1) * LD + n0 + tx*4] = make_float4(hi[0],hi[1],hi[2],hi[3]);
    }
}

// ---------------------------------------------------------------------------
// Einsum with Hermitian reconstruction:
//   G[b,o][k1][k2] = sum_c F[b,c][k1][k2] * W[o,c][k1][k2]
//   rows k1>=256 of F come from conj(F[511-k1][(511-k2)%511]).
// grid (2, 511), 256 threads. Also zeroes G col 511.
__global__ void __launch_bounds__(256) k_einsum(const float* __restrict__ w) {
    int k2 = blockIdx.x * 256 + threadIdx.x;       // 0..511
    int k1 = blockIdx.y;                           // 0..510
    if (k2 == 511) {
        #pragma unroll
        for (int bo = 0; bo < 32; bo++) {
            g_Gr[bo * LD * LD + k1 * LD + 511] = 0.f;
            g_Gi[bo * LD * LD + k1 * LD + 511] = 0.f;
        }
        return;
    }
    float fr[16], fi[16];
    if (k1 < 256) {
        int off = k1 * LD + k2;
        #pragma unroll
        for (int bc = 0; bc < 16; bc++) {
            fr[bc] = g_Fr[bc * (HH*LD) + off];
            fi[bc] = g_Fi[bc * (HH*LD) + off];
        }
    } else {
        int m1 = NF - k1;
        int m2 = (k2 == 0) ? 0 : (NF - k2);
        int off = m1 * LD + m2;
        #pragma unroll
        for (int bc = 0; bc < 16; bc++) {
            fr[bc] =  g_Fr[bc * (HH*LD) + off];
            fi[bc] = -g_Fi[bc * (HH*LD) + off];
        }
    }
    const int wbase = (k1 * NF + k2) * 2;
    const int gidx = k1 * LD + k2;
    #pragma unroll
    for (int o = 0; o < 8; o++) {
        float wr[4], wim[4];
        #pragma unroll
        for (int cc = 0; cc < 4; cc++) {
            int wi = (o * 4 + cc) * (NN2 * 2) + wbase;
            wr[cc]  = w[wi];
            wim[cc] = w[wi + 1];
        }
        #pragma unroll
        for (int b = 0; b < 4; b++) {
            float ar = 0.f, ai = 0.f;
            #pragma unroll
            for (int cc = 0; cc < 4; cc++) {
                float xr = fr[b*4+cc], xi = fi[b*4+cc];
                ar += xr * wr[cc] - xi * wim[cc];
                ai += xr * wim[cc] + xi * wr[cc];
            }
            g_Gr[(b * 8 + o) * (LD*LD) + gidx] = ar;
            g_Gi[(b * 8 + o) * (LD*LD) + gidx] = ai;
        }
    }
}

// Zero row 511 of G (K-padding for the inverse GEMM). grid (32), 512 threads.
__global__ void __launch_bounds__(512) k_zero_grow() {
    int bo = blockIdx.x, i = threadIdx.x;
    g_Gr[bo * LD * LD + 511 * LD + i] = 0.f;
    g_Gi[bo * LD * LD + 511 * LD + i] = 0.f;
}

// ---------------------------------------------------------------------------
// G3: T2[n1][k2] = sum_k1 conj(T[127+n1][k1]) * G[k1][k2]   (cplx NN, conj-A)
// M=256, N=512, K=512 (padded). grid (8, 2, 32)
__global__ void __launch_bounds__(256, 2) k_inv_cols() {
    const int batch = blockIdx.z;
    const int m0 = blockIdx.y * 128;
    const int n0 = blockIdx.x * 64;
    const float* __restrict__ Br = g_Gr + batch * (LD * LD);
    const float* __restrict__ Bi = g_Gi + batch * (LD * LD);
    float* Cr = g_T2r + batch * (HH * LD);
    float* Ci = g_T2i + batch * (HH * LD);

    __shared__ __align__(16) float sAr[8][128], sAi[8][128];
    __shared__ __align__(16) float sBrr[8][128], sBii[8][128], sBnn[8][128];

    const int t = threadIdx.x;
    const int tx = t & 15, ty = t >> 4;
    const int arow = t >> 1, akp = (t & 1) * 4;
    const int bk = t >> 4,  bn4 = (t & 15) * 4;      // B (NN): [k][n], 8x64 (t<128)

    u64 cr[4][4], ci[4][4];
    #pragma unroll
    for (int i = 0; i < 4; i++)
        #pragma unroll
        for (int j = 0; j < 4; j++) { cr[i][j] = 0ull; ci[i][j] = 0ull; }

    float4 va_r, va_i, vb_r, vb_i;
    va_r = *(const float4*)&g_Tr[(CROP0 + m0 + arow) * LD + akp];
    va_i = *(const float4*)&g_Ti[(CROP0 + m0 + arow) * LD + akp];
    if (t < 128) {
        vb_r = *(const float4*)&Br[bk * LD + n0 + bn4];
        vb_i = *(const float4*)&Bi[bk * LD + n0 + bn4];
    }
    const int NCH = LD / 8;
    for (int c = 0; c < NCH; c++) {
        __syncthreads();
        sAr[akp+0][arow] = va_r.x; sAr[akp+1][arow] = va_r.y;
        sAr[akp+2][arow] = va_r.z; sAr[akp+3][arow] = va_r.w;
        sAi[akp+0][arow] = -va_i.x; sAi[akp+1][arow] = -va_i.y;   // conj(A)
        sAi[akp+2][arow] = -va_i.z; sAi[akp+3][arow] = -va_i.w;
        if (t < 128) {
            *(u64*)&sBrr[bk][2*(bn4+0)] = pack2(vb_r.x, vb_r.x);
            *(u64*)&sBrr[bk][2*(bn4+1)] = pack2(vb_r.y, vb_r.y);
            *(u64*)&sBrr[bk][2*(bn4+2)] = pack2(vb_r.z, vb_r.z);
            *(u64*)&sBrr[bk][2*(bn4+3)] = pack2(vb_r.w, vb_r.w);
            *(u64*)&sBii[bk][2*(bn4+0)] = pack2(vb_i.x, vb_i.x);
            *(u64*)&sBii[bk][2*(bn4+1)] = pack2(vb_i.y, vb_i.y);
            *(u64*)&sBii[bk][2*(bn4+2)] = pack2(vb_i.z, vb_i.z);
            *(u64*)&sBii[bk][2*(bn4+3)] = pack2(vb_i.w, vb_i.w);
            *(u64*)&sBnn[bk][2*(bn4+0)] = pack2(-vb_i.x, -vb_i.x);
            *(u64*)&sBnn[bk][2*(bn4+1)] = pack2(-vb_i.y, -vb_i.y);
            *(u64*)&sBnn[bk][2*(bn4+2)] = pack2(-vb_i.z, -vb_i.z);
            *(u64*)&sBnn[bk][2*(bn4+3)] = pack2(-vb_i.w, -vb_i.w);
        }
        __syncthreads();
        if (c + 1 < NCH) {
            int k0 = (c + 1) * 8;
            va_r = *(const float4*)&g_Tr[(CROP0 + m0 + arow) * LD + k0 + akp];
            va_i = *(const float4*)&g_Ti[(CROP0 + m0 + arow) * LD + k0 + akp];
            if (t < 128) {
                vb_r = *(const float4*)&Br[(k0 + bk) * LD + n0 + bn4];
                vb_i = *(const float4*)&Bi[(k0 + bk) * LD + n0 + bn4];
            }
        }
        #pragma unroll
        for (int k = 0; k < 8; k++) {
            ulonglong2 A0 = *(const ulonglong2*)&sAr[k][ty*8];
            ulonglong2 A1 = *(const ulonglong2*)&sAr[k][ty*8+4];
            ulonglong2 E0 = *(const ulonglong2*)&sAi[k][ty*8];
            ulonglong2 E1 = *(const ulonglong2*)&sAi[k][ty*8+4];
            u64 ar[4] = {A0.x, A0.y, A1.x, A1.y};
            u64 ai_[4] = {E0.x, E0.y, E1.x, E1.y};
            #pragma unroll
            for (int j = 0; j < 4; j++) {
                int jj = 2 * (tx*4 + j);
                u64 brr = *(const u64*)&sBrr[k][jj];
                u64 bii = *(const u64*)&sBii[k][jj];
                u64 bnn = *(const u64*)&sBnn[k][jj];
                #pragma unroll
                for (int i2 = 0; i2 < 4; i2++) {
                    fma2(cr[i2][j], ar[i2], brr);
                    fma2(cr[i2][j], ai_[i2], bnn);
                    fma2(ci[i2][j], ar[i2], bii);
                    fma2(ci[i2][j], ai_[i2], brr);
                }
            }
        }
    }
    #pragma unroll
    for (int i2 = 0; i2 < 4; i2++) {
        float lo[4], hi[4];
        int row = m0 + ty * 8 + 2 * i2;
        #pragma unroll
        for (int j = 0; j < 4; j++) unpack2(cr[i2][j], lo[j], hi[j]);
        *(float4*)&Cr[row * LD + n0 + tx*4]     = make_float4(lo[0],lo[1],lo[2],lo[3]);
        *(float4*)&Cr[(row+1) * LD + n0 + tx*4] = make_float4(hi[0],hi[1],hi[2],hi[3]);
        #pragma unroll
        for (int j = 0; j < 4; j++) unpack2(ci[i2][j], lo[j], hi[j]);
        *(float4*)&Ci[row * LD + n0 + tx*4]     = make_float4(lo[0],lo[1],lo[2],lo[3]);
        *(float4*)&Ci[(row+1) * LD + n0 + tx*4] = make_float4(hi[0],hi[1],hi[2],hi[3]);
    }
}

// ---------------------------------------------------------------------------
// G4: out[n1][n2] = (1/511^2) * sum_k2 (T2r*Tr[127+n2][k2] + T2i*Ti[127+n2][k2]) + bias
// M=256, N=256, K=512 (padded). grid (4, 2, 32)
__global__ void __launch_bounds__(256, 2) k_inv_rows(const float* __restrict__ bias,
                                                     float* __restrict__ out) {
    const int batch = blockIdx.z;
    const int m0 = blockIdx.y * 128;
    const int n0 = blockIdx.x * 64;
    const float* __restrict__ Ar = g_T2r + batch * (HH * LD);
    const float* __restrict__ Ai = g_T2i + batch * (HH * LD);
    float* C = out + batch * (HH * HH);
    const float scale = 1.0f / ((float)NF * (float)NF);
    const float bv = bias[batch & 7];

    __shared__ __align__(16) float sAr[8][128], sAi[8][128];
    __shared__ __align__(16) float sBrr[8][128], sBii[8][128];

    const int t = threadIdx.x;
    const int tx = t & 15, ty = t >> 4;
    const int arow = t >> 1, akp = (t & 1) * 4;
    const int bn = t >> 1,  bkp = (t & 1) * 4;       // B (NT): [n][k], 64x8 (t<128)

    u64 cc[4][4];
    #pragma unroll
    for (int i = 0; i < 4; i++)
        #pragma unroll
        for (int j = 0; j < 4; j++) cc[i][j] = 0ull;

    float4 va_r, va_i, vb_r, vb_i;
    va_r = *(const float4*)&Ar[(m0 + arow) * LD + akp];
    va_i = *(const float4*)&Ai[(m0 + arow) * LD + akp];
    if (t < 128) {
        vb_r = *(const float4*)&g_Tr[(CROP0 + n0 + bn) * LD + bkp];
        vb_i = *(const float4*)&g_Ti[(CROP0 + n0 + bn) * LD + bkp];
    }
    const int NCH = LD / 8;
    for (int c = 0; c < NCH; c++) {
        __syncthreads();
        sAr[akp+0][arow] = va_r.x; sAr[akp+1][arow] = va_r.y;
        sAr[akp+2][arow] = va_r.z; sAr[akp+3][arow] = va_r.w;
        sAi[akp+0][arow] = va_i.x; sAi[akp+1][arow] = va_i.y;
        sAi[akp+2][arow] = va_i.z; sAi[akp+3][arow] = va_i.w;
        if (t < 128) {
            *(u64*)&sBrr[bkp+0][2*bn] = pack2(vb_r.x, vb_r.x);
            *(u64*)&sBrr[bkp+1][2*bn] = pack2(vb_r.y, vb_r.y);
            *(u64*)&sBrr[bkp+2][2*bn] = pack2(vb_r.z, vb_r.z);
            *(u64*)&sBrr[bkp+3][2*bn] = pack2(vb_r.w, vb_r.w);
            *(u64*)&sBii[bkp+0][2*bn] = pack2(vb_i.x, vb_i.x);
            *(u64*)&sBii[bkp+1][2*bn] = pack2(vb_i.y, vb_i.y);
            *(u64*)&sBii[bkp+2][2*bn] = pack2(vb_i.z, vb_i.z);
            *(u64*)&sBii[bkp+3][2*bn] = pack2(vb_i.w, vb_i.w);
        }
        __syncthreads();
        if (c + 1 < NCH) {
            int k0 = (c + 1) * 8;
            va_r = *(const float4*)&Ar[(m0 + arow) * LD + k0 + akp];
            va_i = *(const float4*)&Ai[(m0 + arow) * LD + k0 + akp];
            if (t < 128) {
                vb_r = *(const float4*)&g_Tr[(CROP0 + n0 + bn) * LD + k0 + bkp];
                vb_i = *(const float4*)&g_Ti[(CROP0 + n0 + bn) * LD + k0 + bkp];
            }
        }
        #pragma unroll
        for (int k = 0; k < 8; k++) {
            ulonglong2 A0 = *(const ulonglong2*)&sAr[k][ty*8];
            ulonglong2 A1 = *(const ulonglong2*)&sAr[k][ty*8+4];
            ulonglong2 E0 = *(const ulonglong2*)&sAi[k][ty*8];
            ulonglong2 E1 = *(const ulonglong2*)&sAi[k][ty*8+4];
            u64 ar[4] = {A0.x, A0.y, A1.x, A1.y};
            u64 ai_[4] = {E0.x, E0.y, E1.x, E1.y};
            #pragma unroll
            for (int j = 0; j < 4; j++) {
                int jj = 2 * (tx*4 + j);
                u64 brr = *(const u64*)&sBrr[k][jj];
                u64 bii = *(const u64*)&sBii[k][jj];
                #pragma unroll
                for (int i2 = 0; i2 < 4; i2++) {
                    fma2(cc[i2][j], ar[i2], brr);
                    fma2(cc[i2][j], ai_[i2], bii);
                }
            }
        }
    }
    #pragma unroll
    for (int i2 = 0; i2 < 4; i2++) {
        float lo[4], hi[4];
        int row = m0 + ty * 8 + 2 * i2;
        #pragma unroll
        for (int j = 0; j < 4; j++) unpack2(cc[i2][j], lo[j], hi[j]);
        *(float4*)&C[row * HH + n0 + tx*4] =
            make_float4(lo[0]*scale+bv, lo[1]*scale+bv, lo[2]*scale+bv, lo[3]*scale+bv);
        *(float4*)&C[(row+1) * HH + n0 + tx*4] =
            make_float4(hi[0]*scale+bv, hi[1]*scale+bv, hi[2]*scale+bv, hi[3]*scale+bv);
    }
}

// ---------------------------------------------------------------------------
extern "C" void kernel_launch(void* const* d_in, const int* in_sizes, int n_in,
                              void* d_out, int out_size) {
    const float* im   = (const float*)d_in[0];   // (4,4,256,256)
    const float* wgt  = (const float*)d_in[1];   // (8,4,511,511,2)
    const float* bias = (const float*)d_in[2];   // (8,1,1)
    float* out = (float*)d_out;                  // (4,8,256,256)

    k_twiddle<<<(LD * LD) / 256, 256>>>();
    k_fwd_cols<<<dim3(4, 2, 16), 256>>>(im);
    k_fwd_rows<<<dim3(8, 2, 16), 256>>>();
    k_einsum  <<<dim3(2, NF),    256>>>(wgt);
    k_zero_grow<<<32, 512>>>();
    k_inv_cols<<<dim3(8, 2, 32), 256>>>();
    k_inv_rows<<<dim3(4, 2, 32), 256>>>(bias, out);
}

// round 4
// speedup vs baseline: 2.0591x; 1.6170x over previous
#include <cuda_runtime.h>
#include <math_constants.h>

// FourierConv2D via dense DFT matmuls, fp32 with packed f32x2 FMAs.
// Hermitian symmetry exploited BOTH ways:
//   forward: real input -> compute F rows 0..255 only.
//   inverse: out = Re(IFFT(F*W)) = IFFT(F*Wh) where Wh is the Hermitian part
//            of W; H = F.*Wh is Hermitian, so the k1-sum pairs (k1, 511-k1)
//            into 2*Re(...) -> all inverse GEMMs have K/M = 256.
// All 511-wide arrays padded to stride 512 (zeroed pad) -> guard-free GEMMs.

#define NF 511
#define LD 512
#define HH 256
#define CROP0 127
#define NN2 (NF*NF)

typedef unsigned long long u64;

// ---- scratch (device globals; zero-initialized at module load) ----
__device__ float g_Tr[LD*LD],      g_Ti[LD*LD];       // twiddle, padded
__device__ float g_T1r[16*HH*HH],  g_T1i[16*HH*HH];   // [bc][k1<256][n2<256]
__device__ float g_Fr[16*HH*LD],   g_Fi[16*HH*LD];    // [bc][k1<256][k2], col 511 = 0
__device__ float g_Hr[32*HH*LD],   g_Hi[32*HH*LD];    // [bo][k1<256][k2], col 511 = 0
__device__ float g_Ur[32*HH*HH],   g_Ui[32*HH*HH];    // [bo][k1<256][n2<256]

// ---- f32x2 helpers (packed pair carried in a 64-bit integer register) ----
__device__ __forceinline__ void fma2(u64 &d, u64 a, u64 b) {
    asm("fma.rn.f32x2 %0, %1, %2, %0;" : "+l"(d) : "l"(a), "l"(b));
}
__device__ __forceinline__ u64 pack2(float lo, float hi) {
    u64 r; asm("mov.b64 %0, {%1,%2};" : "=l"(r) : "f"(lo), "f"(hi)); return r;
}
__device__ __forceinline__ void unpack2(u64 v, float &lo, float &hi) {
    asm("mov.b64 {%0,%1}, %2;" : "=f"(lo), "=f"(hi) : "l"(v));
}

// ---------------------------------------------------------------------------
// Twiddle: T[a][b] = exp(-2*pi*i*a*b/511), padded row/col 511 zeroed.
__global__ void __launch_bounds__(256) k_twiddle() {
    int p = blockIdx.x * 256 + threadIdx.x;          // covers 512*512
    int a = p >> 9, b = p & 511;
    float cr = 0.f, ci = 0.f;
    if (a < NF && b < NF) {
        int r = (a * b) % NF;
        float ang = (-2.0f * CUDART_PI_F / (float)NF) * (float)r;
        sincosf(ang, &ci, &cr);
    }
    g_Tr[p] = cr;
    g_Ti[p] = ci;
}

// ---------------------------------------------------------------------------
// G1: T1[k1][n2] = sum_{n1<256} T[k1][n1] * x[n1][n2]    (cplx A, real B)
// M=256 (k1), N=256 (n2), K=256. grid (4, 2, 16)
__global__ void __launch_bounds__(256, 2) k_fwd_cols(const float* __restrict__ x) {
    const int batch = blockIdx.z;
    const int m0 = blockIdx.y * 128;
    const int n0 = blockIdx.x * 64;
    const float* __restrict__ B = x + batch * (HH * HH);
    float* Cr = g_T1r + batch * (HH * HH);
    float* Ci = g_T1i + batch * (HH * HH);

    __shared__ __align__(16) float sAr[8][128], sAi[8][128], sB[8][128];

    const int t = threadIdx.x;
    const int tx = t & 15, ty = t >> 4;
    const int arow = t >> 1, akp = (t & 1) * 4;      // A: [m][k], 128x8
    const int bk = t >> 4,  bn4 = (t & 15) * 4;      // B (NN): [k][n], 8x64 (t<128)

    u64 cr[4][4], ci[4][4];
    #pragma unroll
    for (int i = 0; i < 4; i++)
        #pragma unroll
        for (int j = 0; j < 4; j++) { cr[i][j] = 0ull; ci[i][j] = 0ull; }

    float4 va_r, va_i, vb;
    va_r = *(const float4*)&g_Tr[(m0 + arow) * LD + akp];
    va_i = *(const float4*)&g_Ti[(m0 + arow) * LD + akp];
    if (t < 128) vb = *(const float4*)&B[bk * HH + n0 + bn4];

    const int NCH = HH / 8;
    for (int c = 0; c < NCH; c++) {
        __syncthreads();
        sAr[akp+0][arow] = va_r.x; sAr[akp+1][arow] = va_r.y;
        sAr[akp+2][arow] = va_r.z; sAr[akp+3][arow] = va_r.w;
        sAi[akp+0][arow] = va_i.x; sAi[akp+1][arow] = va_i.y;
        sAi[akp+2][arow] = va_i.z; sAi[akp+3][arow] = va_i.w;
        if (t < 128) {
            *(u64*)&sB[bk][2*(bn4+0)] = pack2(vb.x, vb.x);
            *(u64*)&sB[bk][2*(bn4+1)] = pack2(vb.y, vb.y);
            *(u64*)&sB[bk][2*(bn4+2)] = pack2(vb.z, vb.z);
            *(u64*)&sB[bk][2*(bn4+3)] = pack2(vb.w, vb.w);
        }
        __syncthreads();
        if (c + 1 < NCH) {
            int k0 = (c + 1) * 8;
            va_r = *(const float4*)&g_Tr[(m0 + arow) * LD + k0 + akp];
            va_i = *(const float4*)&g_Ti[(m0 + arow) * LD + k0 + akp];
            if (t < 128) vb = *(const float4*)&B[(k0 + bk) * HH + n0 + bn4];
        }
        #pragma unroll
        for (int k = 0; k < 8; k++) {
            ulonglong2 A0 = *(const ulonglong2*)&sAr[k][ty*8];
            ulonglong2 A1 = *(const ulonglong2*)&sAr[k][ty*8+4];
            ulonglong2 E0 = *(const ulonglong2*)&sAi[k][ty*8];
            ulonglong2 E1 = *(const ulonglong2*)&sAi[k][ty*8+4];
            u64 ar[4] = {A0.x, A0.y, A1.x, A1.y};
            u64 ai_[4] = {E0.x, E0.y, E1.x, E1.y};
            #pragma unroll
            for (int j = 0; j < 4; j++) {
                u64 bb = *(const u64*)&sB[k][2*(tx*4+j)];
                #pragma unroll
                for (int i2 = 0; i2 < 4; i2++) {
                    fma2(cr[i2][j], ar[i2], bb);
                    fma2(ci[i2][j], ai_[i2], bb);
                }
            }
        }
    }
    #pragma unroll
    for (int i2 = 0; i2 < 4; i2++) {
        float lo[4], hi[4];
        int row = m0 + ty * 8 + 2 * i2;
        #pragma unroll
        for (int j = 0; j < 4; j++) unpack2(cr[i2][j], lo[j], hi[j]);
        *(float4*)&Cr[row * HH + n0 + tx*4]     = make_float4(lo[0],lo[1],lo[2],lo[3]);
        *(float4*)&Cr[(row+1) * HH + n0 + tx*4] = make_float4(hi[0],hi[1],hi[2],hi[3]);
        #pragma unroll
        for (int j = 0; j < 4; j++) unpack2(ci[i2][j], lo[j], hi[j]);
        *(float4*)&Ci[row * HH + n0 + tx*4]     = make_float4(lo[0],lo[1],lo[2],lo[3]);
        *(float4*)&Ci[(row+1) * HH + n0 + tx*4] = make_float4(hi[0],hi[1],hi[2],hi[3]);
    }
}

// ---------------------------------------------------------------------------
// G2: F[k1][k2] = sum_{n2<256} T1[k1][n2] * T[k2][n2]   (cplx NT)
// M=256, N=512 (row 511 of T is zero -> F col 511 = 0), K=256. grid (8, 2, 16)
__global__ void __launch_bounds__(256, 2) k_fwd_rows() {
    const int batch = blockIdx.z;
    const int m0 = blockIdx.y * 128;
    const int n0 = blockIdx.x * 64;
    const float* __restrict__ Ar = g_T1r + batch * (HH * HH);
    const float* __restrict__ Ai = g_T1i + batch * (HH * HH);
    float* Cr = g_Fr + batch * (HH * LD);
    float* Ci = g_Fi + batch * (HH * LD);

    __shared__ __align__(16) float sAr[8][128], sAi[8][128];
    __shared__ __align__(16) float sBrr[8][128], sBii[8][128], sBnn[8][128];

    const int t = threadIdx.x;
    const int tx = t & 15, ty = t >> 4;
    const int arow = t >> 1, akp = (t & 1) * 4;
    const int bn = t >> 1,  bkp = (t & 1) * 4;       // B (NT): [n][k], 64x8 (t<128)

    u64 cr[4][4], ci[4][4];
    #pragma unroll
    for (int i = 0; i < 4; i++)
        #pragma unroll
        for (int j = 0; j < 4; j++) { cr[i][j] = 0ull; ci[i][j] = 0ull; }

    float4 va_r, va_i, vb_r, vb_i;
    va_r = *(const float4*)&Ar[(m0 + arow) * HH + akp];
    va_i = *(const float4*)&Ai[(m0 + arow) * HH + akp];
    if (t < 128) {
        vb_r = *(const float4*)&g_Tr[(n0 + bn) * LD + bkp];
        vb_i = *(const float4*)&g_Ti[(n0 + bn) * LD + bkp];
    }
    const int NCH = HH / 8;
    for (int c = 0; c < NCH; c++) {
        __syncthreads();
        sAr[akp+0][arow] = va_r.x; sAr[akp+1][arow] = va_r.y;
        sAr[akp+2][arow] = va_r.z; sAr[akp+3][arow] = va_r.w;
        sAi[akp+0][arow] = va_i.x; sAi[akp+1][arow] = va_i.y;
        sAi[akp+2][arow] = va_i.z; sAi[akp+3][arow] = va_i.w;
        if (t < 128) {
            *(u64*)&sBrr[bkp+0][2*bn] = pack2(vb_r.x, vb_r.x);
            *(u64*)&sBrr[bkp+1][2*bn] = pack2(vb_r.y, vb_r.y);
            *(u64*)&sBrr[bkp+2][2*bn] = pack2(vb_r.z, vb_r.z);
            *(u64*)&sBrr[bkp+3][2*bn] = pack2(vb_r.w, vb_r.w);
            *(u64*)&sBii[bkp+0][2*bn] = pack2(vb_i.x, vb_i.x);
            *(u64*)&sBii[bkp+1][2*bn] = pack2(vb_i.y, vb_i.y);
            *(u64*)&sBii[bkp+2][2*bn] = pack2(vb_i.z, vb_i.z);
            *(u64*)&sBii[bkp+3][2*bn] = pack2(vb_i.w, vb_i.w);
            *(u64*)&sBnn[bkp+0][2*bn] = pack2(-vb_i.x, -vb_i.x);
            *(u64*)&sBnn[bkp+1][2*bn] = pack2(-vb_i.y, -vb_i.y);
            *(u64*)&sBnn[bkp+2][2*bn] = pack2(-vb_i.z, -vb_i.z);
            *(u64*)&sBnn[bkp+3][2*bn] = pack2(-vb_i.w, -vb_i.w);
        }
        __syncthreads();
        if (c + 1 < NCH) {
            int k0 = (c + 1) * 8;
            va_r = *(const float4*)&Ar[(m0 + arow) * HH + k0 + akp];
            va_i = *(const float4*)&Ai[(m0 + arow) * HH + k0 + akp];
            if (t < 128) {
                vb_r = *(const float4*)&g_Tr[(n0 + bn) * LD + k0 + bkp];
                vb_i = *(const float4*)&g_Ti[(n0 + bn) * LD + k0 + bkp];
            }
        }
        #pragma unroll
        for (int k = 0; k < 8; k++) {
            ulonglong2 A0 = *(const ulonglong2*)&sAr[k][ty*8];
            ulonglong2 A1 = *(const ulonglong2*)&sAr[k][ty*8+4];
            ulonglong2 E0 = *(const ulonglong2*)&sAi[k][ty*8];
            ulonglong2 E1 = *(const ulonglong2*)&sAi[k][ty*8+4];
            u64 ar[4] = {A0.x, A0.y, A1.x, A1.y};
            u64 ai_[4] = {E0.x, E0.y, E1.x, E1.y};
            #pragma unroll
            for (int j = 0; j < 4; j++) {
                int jj = 2 * (tx*4 + j);
                u64 brr = *(const u64*)&sBrr[k][jj];
                u64 bii = *(const u64*)&sBii[k][jj];
                u64 bnn = *(const u64*)&sBnn[k][jj];
                #pragma unroll
                for (int i2 = 0; i2 < 4; i2++) {
                    fma2(cr[i2][j], ar[i2], brr);
                    fma2(cr[i2][j], ai_[i2], bnn);
                    fma2(ci[i2][j], ar[i2], bii);
                    fma2(ci[i2][j], ai_[i2], brr);
                }
            }
        }
    }
    #pragma unroll
    for (int i2 = 0; i2 < 4; i2++) {
        float lo[4], hi[4];
        int row = m0 + ty * 8 + 2 * i2;
        #pragma unroll
        for (int j = 0; j < 4; j++) unpack2(cr[i2][j], lo[j], hi[j]);
        *(float4*)&Cr[row * LD + n0 + tx*4]     = make_float4(lo[0],lo[1],lo[2],lo[3]);
        *(float4*)&Cr[(row+1) * LD + n0 + tx*4] = make_float4(hi[0],hi[1],hi[2],hi[3]);
        #pragma unroll
        for (int j = 0; j < 4; j++) unpack2(ci[i2][j], lo[j], hi[j]);
        *(float4*)&Ci[row * LD + n0 + tx*4]     = make_float4(lo[0],lo[1],lo[2],lo[3]);
        *(float4*)&Ci[(row+1) * LD + n0 + tx*4] = make_float4(hi[0],hi[1],hi[2],hi[3]);
    }
}

// ---------------------------------------------------------------------------
// Einsum with Hermitian weight projection:
//   Wh(k) = (W(k) + conj(W(-k)))/2   (only Wh contributes to Re(IFFT))
//   H[b,o][k1][k2] = s * sum_c F[b,c][k1][k2] * Wh[o,c][k1][k2],
//   s = 0.5 for k1==0, 1.0 for k1>=1 (0.5 from Wh, x2 from (k1,511-k1) pairing).
// Only rows k1=0..255 needed. grid (2, 256), 256 threads. Zeroes H col 511.
__global__ void __launch_bounds__(256) k_einsum_h(const float* __restrict__ w) {
    int k2 = blockIdx.x * 256 + threadIdx.x;       // 0..511
    int k1 = blockIdx.y;                           // 0..255
    if (k2 == 511) {
        #pragma unroll
        for (int bo = 0; bo < 32; bo++) {
            g_Hr[bo * (HH*LD) + k1 * LD + 511] = 0.f;
            g_Hi[bo * (HH*LD) + k1 * LD + 511] = 0.f;
        }
        return;
    }
    float fr[16], fi[16];
    {
        int off = k1 * LD + k2;
        #pragma unroll
        for (int bc = 0; bc < 16; bc++) {
            fr[bc] = g_Fr[bc * (HH*LD) + off];
            fi[bc] = g_Fi[bc * (HH*LD) + off];
        }
    }
    const int m1 = (k1 == 0) ? 0 : (NF - k1);
    const int m2 = (k2 == 0) ? 0 : (NF - k2);
    const int wbase  = (k1 * NF + k2) * 2;
    const int wmbase = (m1 * NF + m2) * 2;
    const float s = (k1 == 0) ? 0.5f : 1.0f;
    const int hidx = k1 * LD + k2;
    #pragma unroll
    for (int o = 0; o < 8; o++) {
        float whr[4], whi[4];
        #pragma unroll
        for (int cc = 0; cc < 4; cc++) {
            int base  = (o * 4 + cc) * (NN2 * 2);
            float w1r = w[base + wbase],  w1i = w[base + wbase + 1];
            float w2r = w[base + wmbase], w2i = w[base + wmbase + 1];
            whr[cc] = s * (w1r + w2r);
            whi[cc] = s * (w1i - w2i);
        }
        #pragma unroll
        for (int b = 0; b < 4; b++) {
            float ar = 0.f, ai = 0.f;
            #pragma unroll
            for (int cc = 0; cc < 4; cc++) {
                float xr = fr[b*4+cc], xi = fi[b*4+cc];
                ar += xr * whr[cc] - xi * whi[cc];
                ai += xr * whi[cc] + xi * whr[cc];
            }
            g_Hr[(b * 8 + o) * (HH*LD) + hidx] = ar;
            g_Hi[(b * 8 + o) * (HH*LD) + hidx] = ai;
        }
    }
}

// ---------------------------------------------------------------------------
// U[k1][n2] = sum_{k2} H[k1][k2] * conj(T[127+n2][k2])   (cplx NT, conj-B)
//   re += Hr*Tr + Hi*Ti ;  im += Hi*Tr - Hr*Ti
// M=256 (k1), N=256 (n2), K=512 (padded). grid (4, 2, 32)
__global__ void __launch_bounds__(256, 2) k_inv_u() {
    const int batch = blockIdx.z;
    const int m0 = blockIdx.y * 128;
    const int n0 = blockIdx.x * 64;
    const float* __restrict__ Ar = g_Hr + batch * (HH * LD);
    const float* __restrict__ Ai = g_Hi + batch * (HH * LD);
    float* Cr = g_Ur + batch * (HH * HH);
    float* Ci = g_Ui + batch * (HH * HH);

    __shared__ __align__(16) float sAr[8][128], sAi[8][128];
    __shared__ __align__(16) float sBrr[8][128], sBii[8][128], sBni[8][128];

    const int t = threadIdx.x;
    const int tx = t & 15, ty = t >> 4;
    const int arow = t >> 1, akp = (t & 1) * 4;
    const int bn = t >> 1,  bkp = (t & 1) * 4;       // B (NT): [n][k], 64x8 (t<128)

    u64 cr[4][4], ci[4][4];
    #pragma unroll
    for (int i = 0; i < 4; i++)
        #pragma unroll
        for (int j = 0; j < 4; j++) { cr[i][j] = 0ull; ci[i][j] = 0ull; }

    float4 va_r, va_i, vb_r, vb_i;
    va_r = *(const float4*)&Ar[(m0 + arow) * LD + akp];
    va_i = *(const float4*)&Ai[(m0 + arow) * LD + akp];
    if (t < 128) {
        vb_r = *(const float4*)&g_Tr[(CROP0 + n0 + bn) * LD + bkp];
        vb_i = *(const float4*)&g_Ti[(CROP0 + n0 + bn) * LD + bkp];
    }
    const int NCH = LD / 8;
    for (int c = 0; c < NCH; c++) {
        __syncthreads();
        sAr[akp+0][arow] = va_r.x; sAr[akp+1][arow] = va_r.y;
        sAr[akp+2][arow] = va_r.z; sAr[akp+3][arow] = va_r.w;
        sAi[akp+0][arow] = va_i.x; sAi[akp+1][arow] = va_i.y;
        sAi[akp+2][arow] = va_i.z; sAi[akp+3][arow] = va_i.w;
        if (t < 128) {
            *(u64*)&sBrr[bkp+0][2*bn] = pack2(vb_r.x, vb_r.x);
            *(u64*)&sBrr[bkp+1][2*bn] = pack2(vb_r.y, vb_r.y);
            *(u64*)&sBrr[bkp+2][2*bn] = pack2(vb_r.z, vb_r.z);
            *(u64*)&sBrr[bkp+3][2*bn] = pack2(vb_r.w, vb_r.w);
            *(u64*)&sBii[bkp+0][2*bn] = pack2(vb_i.x, vb_i.x);
            *(u64*)&sBii[bkp+1][2*bn] = pack2(vb_i.y, vb_i.y);
            *(u64*)&sBii[bkp+2][2*bn] = pack2(vb_i.z, vb_i.z);
            *(u64*)&sBii[bkp+3][2*bn] = pack2(vb_i.w, vb_i.w);
            *(u64*)&sBni[bkp+0][2*bn] = pack2(-vb_i.x, -vb_i.x);
            *(u64*)&sBni[bkp+1][2*bn] = pack2(-vb_i.y, -vb_i.y);
            *(u64*)&sBni[bkp+2][2*bn] = pack2(-vb_i.z, -vb_i.z);
            *(u64*)&sBni[bkp+3][2*bn] = pack2(-vb_i.w, -vb_i.w);
        }
        __syncthreads();
        if (c + 1 < NCH) {
            int k0 = (c + 1) * 8;
            va_r = *(const float4*)&Ar[(m0 + arow) * LD + k0 + akp];
            va_i = *(const float4*)&Ai[(m0 + arow) * LD + k0 + akp];
            if (t < 128) {
                vb_r = *(const float4*)&g_Tr[(CROP0 + n0 + bn) * LD + k0 + bkp];
                vb_i = *(const float4*)&g_Ti[(CROP0 + n0 + bn) * LD + k0 + bkp];
            }
        }
        #pragma unroll
        for (int k = 0; k < 8; k++) {
            ulonglong2 A0 = *(const ulonglong2*)&sAr[k][ty*8];
            ulonglong2 A1 = *(const ulonglong2*)&sAr[k][ty*8+4];
            ulonglong2 E0 = *(const ulonglong2*)&sAi[k][ty*8];
            ulonglong2 E1 = *(const ulonglong2*)&sAi[k][ty*8+4];
            u64 ar[4] = {A0.x, A0.y, A1.x, A1.y};
            u64 ai_[4] = {E0.x, E0.y, E1.x, E1.y};
            #pragma unroll
            for (int j = 0; j < 4; j++) {
                int jj = 2 * (tx*4 + j);
                u64 brr = *(const u64*)&sBrr[k][jj];
                u64 bii = *(const u64*)&sBii[k][jj];
                u64 bni = *(const u64*)&sBni[k][jj];
                #pragma unroll
                for (int i2 = 0; i2 < 4; i2++) {
                    fma2(cr[i2][j], ar[i2], brr);
                    fma2(cr[i2][j], ai_[i2], bii);
                    fma2(ci[i2][j], ai_[i2], brr);
                    fma2(ci[i2][j], ar[i2], bni);
                }
            }
        }
    }
    #pragma unroll
    for (int i2 = 0; i2 < 4; i2++) {
        float lo[4], hi[4];
        int row = m0 + ty * 8 + 2 * i2;
        #pragma unroll
        for (int j = 0; j < 4; j++) unpack2(cr[i2][j], lo[j], hi[j]);
        *(float4*)&Cr[row * HH + n0 + tx*4]     = make_float4(lo[0],lo[1],lo[2],lo[3]);
        *(float4*)&Cr[(row+1) * HH + n0 + tx*4] = make_float4(hi[0],hi[1],hi[2],hi[3]);
        #pragma unroll
        for (int j = 0; j < 4; j++) unpack2(ci[i2][j], lo[j], hi[j]);
        *(float4*)&Ci[row * HH + n0 + tx*4]     = make_float4(lo[0],lo[1],lo[2],lo[3]);
        *(float4*)&Ci[(row+1) * HH + n0 + tx*4] = make_float4(hi[0],hi[1],hi[2],hi[3]);
    }
}

// ---------------------------------------------------------------------------
// out[n1][n2] = (1/511^2) * Re{ sum_{k1<256} conj(T[127+n1][k1]) * U[k1][n2] } + bias
//             = scale * sum_k1 (Tr*Ur + Ti*Ui) + bias      (cplx NN, real out)
// M=256, N=256, K=256. grid (4, 2, 32)
__global__ void __launch_bounds__(256, 2) k_out(const float* __restrict__ bias,
                                               float* __restrict__ out) {
    const int batch = blockIdx.z;
    const int m0 = blockIdx.y * 128;
    const int n0 = blockIdx.x * 64;
    const float* __restrict__ Br = g_Ur + batch * (HH * HH);
    const float* __restrict__ Bi = g_Ui + batch * (HH * HH);
    float* C = out + batch * (HH * HH);
    const float scale = 1.0f / ((float)NF * (float)NF);
    const float bv = bias[batch & 7];

    __shared__ __align__(16) float sAr[8][128], sAi[8][128];
    __shared__ __align__(16) float sBr[8][128], sBi[8][128];

    const int t = threadIdx.x;
    const int tx = t & 15, ty = t >> 4;
    const int arow = t >> 1, akp = (t & 1) * 4;
    const int bk = t >> 4,  bn4 = (t & 15) * 4;      // B (NN): [k][n], 8x64 (t<128)

    u64 cc[4][4];
    #pragma unroll
    for (int i = 0; i < 4; i++)
        #pragma unroll
        for (int j = 0; j < 4; j++) cc[i][j] = 0ull;

    float4 va_r, va_i, vb_r, vb_i;
    va_r = *(const float4*)&g_Tr[(CROP0 + m0 + arow) * LD + akp];
    va_i = *(const float4*)&g_Ti[(CROP0 + m0 + arow) * LD + akp];
    if (t < 128) {
        vb_r = *(const float4*)&Br[bk * HH + n0 + bn4];
        vb_i = *(const float4*)&Bi[bk * HH + n0 + bn4];
    }
    const int NCH = HH / 8;
    for (int c = 0; c < NCH; c++) {
        __syncthreads();
        sAr[akp+0][arow] = va_r.x; sAr[akp+1][arow] = va_r.y;
        sAr[akp+2][arow] = va_r.z; sAr[akp+3][arow] = va_r.w;
        sAi[akp+0][arow] = va_i.x; sAi[akp+1][arow] = va_i.y;
        sAi[akp+2][arow] = va_i.z; sAi[akp+3][arow] = va_i.w;
        if (t < 128) {
            *(u64*)&sBr[bk][2*(bn4+0)] = pack2(vb_r.x, vb_r.x);
            *(u64*)&sBr[bk][2*(bn4+1)] = pack2(vb_r.y, vb_r.y);
            *(u64*)&sBr[bk][2*(bn4+2)] = pack2(vb_r.z, vb_r.z);
            *(u64*)&sBr[bk][2*(bn4+3)] = pack2(vb_r.w, vb_r.w);
            *(u64*)&sBi[bk][2*(bn4+0)] = pack2(vb_i.x, vb_i.x);
            *(u64*)&sBi[bk][2*(bn4+1)] = pack2(vb_i.y, vb_i.y);
            *(u64*)&sBi[bk][2*(bn4+2)] = pack2(vb_i.z, vb_i.z);
            *(u64*)&sBi[bk][2*(bn4+3)] = pack2(vb_i.w, vb_i.w);
        }
        __syncthreads();
        if (c + 1 < NCH) {
            int k0 = (c + 1) * 8;
            va_r = *(const float4*)&g_Tr[(CROP0 + m0 + arow) * LD + k0 + akp];
            va_i = *(const float4*)&g_Ti[(CROP0 + m0 + arow) * LD + k0 + akp];
            if (t < 128) {
                vb_r = *(const float4*)&Br[(k0 + bk) * HH + n0 + bn4];
                vb_i = *(const float4*)&Bi[(k0 + bk) * HH + n0 + bn4];
            }
        }
        #pragma unroll
        for (int k = 0; k < 8; k++) {
            ulonglong2 A0 = *(const ulonglong2*)&sAr[k][ty*8];
            ulonglong2 A1 = *(const ulonglong2*)&sAr[k][ty*8+4];
            ulonglong2 E0 = *(const ulonglong2*)&sAi[k][ty*8];
            ulonglong2 E1 = *(const ulonglong2*)&sAi[k][ty*8+4];
            u64 ar[4] = {A0.x, A0.y, A1.x, A1.y};
            u64 ai_[4] = {E0.x, E0.y, E1.x, E1.y};
            #pragma unroll
            for (int j = 0; j < 4; j++) {
                int jj = 2 * (tx*4 + j);
                u64 br = *(const u64*)&sBr[k][jj];
                u64 bi = *(const u64*)&sBi[k][jj];
                #pragma unroll
                for (int i2 = 0; i2 < 4; i2++) {
                    fma2(cc[i2][j], ar[i2], br);
                    fma2(cc[i2][j], ai_[i2], bi);
                }
            }
        }
    }
    #pragma unroll
    for (int i2 = 0; i2 < 4; i2++) {
        float lo[4], hi[4];
        int row = m0 + ty * 8 + 2 * i2;
        #pragma unroll
        for (int j = 0; j < 4; j++) unpack2(cc[i2][j], lo[j], hi[j]);
        *(float4*)&C[row * HH + n0 + tx*4] =
            make_float4(lo[0]*scale+bv, lo[1]*scale+bv, lo[2]*scale+bv, lo[3]*scale+bv);
        *(float4*)&C[(row+1) * HH + n0 + tx*4] =
            make_float4(hi[0]*scale+bv, hi[1]*scale+bv, hi[2]*scale+bv, hi[3]*scale+bv);
    }
}

// ---------------------------------------------------------------------------
extern "C" void kernel_launch(void* const* d_in, const int* in_sizes, int n_in,
                              void* d_out, int out_size) {
    const float* im   = (const float*)d_in[0];   // (4,4,256,256)
    const float* wgt  = (const float*)d_in[1];   // (8,4,511,511,2)
    const float* bias = (const float*)d_in[2];   // (8,1,1)
    float* out = (float*)d_out;                  // (4,8,256,256)

    k_twiddle <<<(LD * LD) / 256, 256>>>();
    k_fwd_cols<<<dim3(4, 2, 16), 256>>>(im);
    k_fwd_rows<<<dim3(8, 2, 16), 256>>>();
    k_einsum_h<<<dim3(2, 256),   256>>>(wgt);
    k_inv_u   <<<dim3(4, 2, 32), 256>>>();
    k_out     <<<dim3(4, 2, 32), 256>>>(bias, out);
}

// round 6
// speedup vs baseline: 2.7916x; 1.3558x over previous
#include <cuda_runtime.h>
#include <cuda_bf16.h>
#include <math_constants.h>
#include <cstdint>

// FourierConv2D via DFT matmuls. Forward + small GEMMs: fp32 FFMA2 scalar.
// inv_u (largest GEMM): mma.sync bf16 split-precision (hi/lo, lo*lo dropped).
// (tcgen05 is unavailable: harness ptxas targets sm_103 without the 'a' ISA.)

#define NF 511
#define LD 512
#define HH 256
#define CROP0 127
#define NN2 (NF*NF)

typedef unsigned long long u64;

// ---- scratch (device globals) ----
__device__ float g_Tr[LD*LD],      g_Ti[LD*LD];
__device__ float g_T1r[16*HH*HH],  g_T1i[16*HH*HH];
__device__ float g_Fr[16*HH*LD],   g_Fi[16*HH*LD];
__device__ float g_Ur[32*HH*HH],   g_Ui[32*HH*HH];
// split-bf16 H (einsum output) and B (twiddle-derived) for tensor inv_u
__device__ __nv_bfloat16 g_Hrh[32*HH*LD], g_Hrl[32*HH*LD];
__device__ __nv_bfloat16 g_Hih[32*HH*LD], g_Hil[32*HH*LD];
__device__ __nv_bfloat16 g_Brh[LD*LD], g_Bih[LD*LD], g_Brl[LD*LD], g_Bil[LD*LD];

// ---- f32x2 helpers ----
__device__ __forceinline__ void fma2(u64 &d, u64 a, u64 b) {
    asm("fma.rn.f32x2 %0, %1, %2, %0;" : "+l"(d) : "l"(a), "l"(b));
}
__device__ __forceinline__ u64 pack2(float lo, float hi) {
    u64 r; asm("mov.b64 %0, {%1,%2};" : "=l"(r) : "f"(lo), "f"(hi)); return r;
}
__device__ __forceinline__ void unpack2(u64 v, float &lo, float &hi) {
    asm("mov.b64 {%0,%1}, %2;" : "=f"(lo), "=f"(hi) : "l"(v));
}
__device__ __forceinline__ void split_bf16(float v, __nv_bfloat16 &h, __nv_bfloat16 &l) {
    h = __float2bfloat16(v);
    l = __float2bfloat16(v - __bfloat162float(h));
}

// ---- mma.sync helpers ----
__device__ __forceinline__ uint32_t smem_u32(const void* p) {
    uint32_t a;
    asm("{ .reg .u64 t; cvta.to.shared.u64 t, %1; cvt.u32.u64 %0, t; }" : "=r"(a) : "l"(p));
    return a;
}
__device__ __forceinline__ void ldsm_x4(uint32_t &r0, uint32_t &r1, uint32_t &r2, uint32_t &r3,
                                        uint32_t addr) {
    asm volatile("ldmatrix.sync.aligned.m8n8.x4.shared.b16 {%0,%1,%2,%3}, [%4];"
                 : "=r"(r0), "=r"(r1), "=r"(r2), "=r"(r3) : "r"(addr));
}
__device__ __forceinline__ void ldsm_x2(uint32_t &r0, uint32_t &r1, uint32_t addr) {
    asm volatile("ldmatrix.sync.aligned.m8n8.x2.shared.b16 {%0,%1}, [%2];"
                 : "=r"(r0), "=r"(r1) : "r"(addr));
}
__device__ __forceinline__ void mma_bf16(float* c, const uint32_t* a, const uint32_t* b) {
    asm volatile("mma.sync.aligned.m16n8k16.row.col.f32.bf16.bf16.f32 "
                 "{%0,%1,%2,%3}, {%4,%5,%6,%7}, {%8,%9}, {%0,%1,%2,%3};"
                 : "+f"(c[0]), "+f"(c[1]), "+f"(c[2]), "+f"(c[3])
                 : "r"(a[0]), "r"(a[1]), "r"(a[2]), "r"(a[3]), "r"(b[0]), "r"(b[1]));
}

// ---------------------------------------------------------------------------
__global__ void __launch_bounds__(256) k_twiddle() {
    int p = blockIdx.x * 256 + threadIdx.x;
    int a = p >> 9, b = p & 511;
    float cr = 0.f, ci = 0.f;
    if (a < NF && b < NF) {
        int r = (a * b) % NF;
        float ang = (-2.0f * CUDART_PI_F / (float)NF) * (float)r;
        sincosf(ang, &ci, &cr);
    }
    g_Tr[p] = cr;
    g_Ti[p] = ci;
}

// B operand prep: rows 0..255 -> (Tr, Ti) at row 127+n; rows 256..511 -> (-Ti, Tr).
__global__ void __launch_bounds__(256) k_prep_binv() {
    int p = blockIdx.x * 256 + threadIdx.x;    // 512*512
    int n = p >> 9, k = p & 511;
    float br, bi;
    if (n < 256) {
        br = g_Tr[(CROP0 + n) * LD + k];
        bi = g_Ti[(CROP0 + n) * LD + k];
    } else {
        int m = n - 256;
        br = -g_Ti[(CROP0 + m) * LD + k];
        bi =  g_Tr[(CROP0 + m) * LD + k];
    }
    __nv_bfloat16 h, l;
    split_bf16(br, h, l);  g_Brh[p] = h;  g_Brl[p] = l;
    split_bf16(bi, h, l);  g_Bih[p] = h;  g_Bil[p] = l;
}

// ---------------------------------------------------------------------------
// G1: T1[k1][n2] = sum_{n1<256} T[k1][n1] * x[n1][n2]  (cplx A, real B), scalar FFMA2
__global__ void __launch_bounds__(256, 2) k_fwd_cols(const float* __restrict__ x) {
    const int batch = blockIdx.z;
    const int m0 = blockIdx.y * 128;
    const int n0 = blockIdx.x * 64;
    const float* __restrict__ B = x + batch * (HH * HH);
    float* Cr = g_T1r + batch * (HH * HH);
    float* Ci = g_T1i + batch * (HH * HH);

    __shared__ __align__(16) float sAr[8][128], sAi[8][128], sB[8][128];
    const int t = threadIdx.x;
    const int tx = t & 15, ty = t >> 4;
    const int arow = t >> 1, akp = (t & 1) * 4;
    const int bk = t >> 4,  bn4 = (t & 15) * 4;

    u64 cr[4][4], ci[4][4];
    #pragma unroll
    for (int i = 0; i < 4; i++)
        #pragma unroll
        for (int j = 0; j < 4; j++) { cr[i][j] = 0ull; ci[i][j] = 0ull; }

    float4 va_r, va_i, vb;
    va_r = *(const float4*)&g_Tr[(m0 + arow) * LD + akp];
    va_i = *(const float4*)&g_Ti[(m0 + arow) * LD + akp];
    if (t < 128) vb = *(const float4*)&B[bk * HH + n0 + bn4];

    const int NCH = HH / 8;
    for (int c = 0; c < NCH; c++) {
        __syncthreads();
        sAr[akp+0][arow] = va_r.x; sAr[akp+1][arow] = va_r.y;
        sAr[akp+2][arow] = va_r.z; sAr[akp+3][arow] = va_r.w;
        sAi[akp+0][arow] = va_i.x; sAi[akp+1][arow] = va_i.y;
        sAi[akp+2][arow] = va_i.z; sAi[akp+3][arow] = va_i.w;
        if (t < 128) {
            *(u64*)&sB[bk][2*(bn4+0)] = pack2(vb.x, vb.x);
            *(u64*)&sB[bk][2*(bn4+1)] = pack2(vb.y, vb.y);
            *(u64*)&sB[bk][2*(bn4+2)] = pack2(vb.z, vb.z);
            *(u64*)&sB[bk][2*(bn4+3)] = pack2(vb.w, vb.w);
        }
        __syncthreads();
        if (c + 1 < NCH) {
            int k0 = (c + 1) * 8;
            va_r = *(const float4*)&g_Tr[(m0 + arow) * LD + k0 + akp];
            va_i = *(const float4*)&g_Ti[(m0 + arow) * LD + k0 + akp];
            if (t < 128) vb = *(const float4*)&B[(k0 + bk) * HH + n0 + bn4];
        }
        #pragma unroll
        for (int k = 0; k < 8; k++) {
            ulonglong2 A0 = *(const ulonglong2*)&sAr[k][ty*8];
            ulonglong2 A1 = *(const ulonglong2*)&sAr[k][ty*8+4];
            ulonglong2 E0 = *(const ulonglong2*)&sAi[k][ty*8];
            ulonglong2 E1 = *(const ulonglong2*)&sAi[k][ty*8+4];
            u64 ar[4] = {A0.x, A0.y, A1.x, A1.y};
            u64 ai_[4] = {E0.x, E0.y, E1.x, E1.y};
            #pragma unroll
            for (int j = 0; j < 4; j++) {
                u64 bb = *(const u64*)&sB[k][2*(tx*4+j)];
                #pragma unroll
                for (int i2 = 0; i2 < 4; i2++) {
                    fma2(cr[i2][j], ar[i2], bb);
                    fma2(ci[i2][j], ai_[i2], bb);
                }
            }
        }
    }
    #pragma unroll
    for (int i2 = 0; i2 < 4; i2++) {
        float lo[4], hi[4];
        int row = m0 + ty * 8 + 2 * i2;
        #pragma unroll
        for (int j = 0; j < 4; j++) unpack2(cr[i2][j], lo[j], hi[j]);
        *(float4*)&Cr[row * HH + n0 + tx*4]     = make_float4(lo[0],lo[1],lo[2],lo[3]);
        *(float4*)&Cr[(row+1) * HH + n0 + tx*4] = make_float4(hi[0],hi[1],hi[2],hi[3]);
        #pragma unroll
        for (int j = 0; j < 4; j++) unpack2(ci[i2][j], lo[j], hi[j]);
        *(float4*)&Ci[row * HH + n0 + tx*4]     = make_float4(lo[0],lo[1],lo[2],lo[3]);
        *(float4*)&Ci[(row+1) * HH + n0 + tx*4] = make_float4(hi[0],hi[1],hi[2],hi[3]);
    }
}

// ---------------------------------------------------------------------------
// G2: F[k1][k2] = sum_{n2<256} T1[k1][n2] * T[k2][n2]  (cplx NT), scalar FFMA2
__global__ void __launch_bounds__(256, 2) k_fwd_rows() {
    const int batch = blockIdx.z;
    const int m0 = blockIdx.y * 128;
    const int n0 = blockIdx.x * 64;
    const float* __restrict__ Ar = g_T1r + batch * (HH * HH);
    const float* __restrict__ Ai = g_T1i + batch * (HH * HH);
    float* Cr = g_Fr + batch * (HH * LD);
    float* Ci = g_Fi + batch * (HH * LD);

    __shared__ __align__(16) float sAr[8][128], sAi[8][128];
    __shared__ __align__(16) float sBrr[8][128], sBii[8][128], sBnn[8][128];

    const int t = threadIdx.x;
    const int tx = t & 15, ty = t >> 4;
    const int arow = t >> 1, akp = (t & 1) * 4;
    const int bn = t >> 1,  bkp = (t & 1) * 4;

    u64 cr[4][4], ci[4][4];
    #pragma unroll
    for (int i = 0; i < 4; i++)
        #pragma unroll
        for (int j = 0; j < 4; j++) { cr[i][j] = 0ull; ci[i][j] = 0ull; }

    float4 va_r, va_i, vb_r, vb_i;
    va_r = *(const float4*)&Ar[(m0 + arow) * HH + akp];
    va_i = *(const float4*)&Ai[(m0 + arow) * HH + akp];
    if (t < 128) {
        vb_r = *(const float4*)&g_Tr[(n0 + bn) * LD + bkp];
        vb_i = *(const float4*)&g_Ti[(n0 + bn) * LD + bkp];
    }
    const int NCH = HH / 8;
    for (int c = 0; c < NCH; c++) {
        __syncthreads();
        sAr[akp+0][arow] = va_r.x; sAr[akp+1][arow] = va_r.y;
        sAr[akp+2][arow] = va_r.z; sAr[akp+3][arow] = va_r.w;
        sAi[akp+0][arow] = va_i.x; sAi[akp+1][arow] = va_i.y;
        sAi[akp+2][arow] = va_i.z; sAi[akp+3][arow] = va_i.w;
        if (t < 128) {
            *(u64*)&sBrr[bkp+0][2*bn] = pack2(vb_r.x, vb_r.x);
            *(u64*)&sBrr[bkp+1][2*bn] = pack2(vb_r.y, vb_r.y);
            *(u64*)&sBrr[bkp+2][2*bn] = pack2(vb_r.z, vb_r.z);
            *(u64*)&sBrr[bkp+3][2*bn] = pack2(vb_r.w, vb_r.w);
            *(u64*)&sBii[bkp+0][2*bn] = pack2(vb_i.x, vb_i.x);
            *(u64*)&sBii[bkp+1][2*bn] = pack2(vb_i.y, vb_i.y);
            *(u64*)&sBii[bkp+2][2*bn] = pack2(vb_i.z, vb_i.z);
            *(u64*)&sBii[bkp+3][2*bn] = pack2(vb_i.w, vb_i.w);
            *(u64*)&sBnn[bkp+0][2*bn] = pack2(-vb_i.x, -vb_i.x);
            *(u64*)&sBnn[bkp+1][2*bn] = pack2(-vb_i.y, -vb_i.y);
            *(u64*)&sBnn[bkp+2][2*bn] = pack2(-vb_i.z, -vb_i.z);
            *(u64*)&sBnn[bkp+3][2*bn] = pack2(-vb_i.w, -vb_i.w);
        }
        __syncthreads();
        if (c + 1 < NCH) {
            int k0 = (c + 1) * 8;
            va_r = *(const float4*)&Ar[(m0 + arow) * HH + k0 + akp];
            va_i = *(const float4*)&Ai[(m0 + arow) * HH + k0 + akp];
            if (t < 128) {
                vb_r = *(const float4*)&g_Tr[(n0 + bn) * LD + k0 + bkp];
                vb_i = *(const float4*)&g_Ti[(n0 + bn) * LD + k0 + bkp];
            }
        }
        #pragma unroll
        for (int k = 0; k < 8; k++) {
            ulonglong2 A0 = *(const ulonglong2*)&sAr[k][ty*8];
            ulonglong2 A1 = *(const ulonglong2*)&sAr[k][ty*8+4];
            ulonglong2 E0 = *(const ulonglong2*)&sAi[k][ty*8];
            ulonglong2 E1 = *(const ulonglong2*)&sAi[k][ty*8+4];
            u64 ar[4] = {A0.x, A0.y, A1.x, A1.y};
            u64 ai_[4] = {E0.x, E0.y, E1.x, E1.y};
            #pragma unroll
            for (int j = 0; j < 4; j++) {
                int jj = 2 * (tx*4 + j);
                u64 brr = *(const u64*)&sBrr[k][jj];
                u64 bii = *(const u64*)&sBii[k][jj];
                u64 bnn = *(const u64*)&sBnn[k][jj];
                #pragma unroll
                for (int i2 = 0; i2 < 4; i2++) {
                    fma2(cr[i2][j], ar[i2], brr);
                    fma2(cr[i2][j], ai_[i2], bnn);
                    fma2(ci[i2][j], ar[i2], bii);
                    fma2(ci[i2][j], ai_[i2], brr);
                }
            }
        }
    }
    #pragma unroll
    for (int i2 = 0; i2 < 4; i2++) {
        float lo[4], hi[4];
        int row = m0 + ty * 8 + 2 * i2;
        #pragma unroll
        for (int j = 0; j < 4; j++) unpack2(cr[i2][j], lo[j], hi[j]);
        *(float4*)&Cr[row * LD + n0 + tx*4]     = make_float4(lo[0],lo[1],lo[2],lo[3]);
        *(float4*)&Cr[(row+1) * LD + n0 + tx*4] = make_float4(hi[0],hi[1],hi[2],hi[3]);
        #pragma unroll
        for (int j = 0; j < 4; j++) unpack2(ci[i2][j], lo[j], hi[j]);
        *(float4*)&Ci[row * LD + n0 + tx*4]     = make_float4(lo[0],lo[1],lo[2],lo[3]);
        *(float4*)&Ci[(row+1) * LD + n0 + tx*4] = make_float4(hi[0],hi[1],hi[2],hi[3]);
    }
}

// ---------------------------------------------------------------------------
// Einsum with Hermitian weight projection; outputs split-bf16 H for the MMA.
__global__ void __launch_bounds__(256) k_einsum_h(const float* __restrict__ w) {
    int k2 = blockIdx.x * 256 + threadIdx.x;       // 0..511
    int k1 = blockIdx.y;                           // 0..255
    if (k2 == 511) {
        #pragma unroll
        for (int bo = 0; bo < 32; bo++) {
            int idx = bo * (HH*LD) + k1 * LD + 511;
            g_Hrh[idx] = __float2bfloat16(0.f); g_Hrl[idx] = __float2bfloat16(0.f);
            g_Hih[idx] = __float2bfloat16(0.f); g_Hil[idx] = __float2bfloat16(0.f);
        }
        return;
    }
    float fr[16], fi[16];
    {
        int off = k1 * LD + k2;
        #pragma unroll
        for (int bc = 0; bc < 16; bc++) {
            fr[bc] = g_Fr[bc * (HH*LD) + off];
            fi[bc] = g_Fi[bc * (HH*LD) + off];
        }
    }
    const int m1 = (k1 == 0) ? 0 : (NF - k1);
    const int m2 = (k2 == 0) ? 0 : (NF - k2);
    const int wbase  = (k1 * NF + k2) * 2;
    const int wmbase = (m1 * NF + m2) * 2;
    const float s = (k1 == 0) ? 0.5f : 1.0f;
    const int hidx = k1 * LD + k2;
    #pragma unroll
    for (int o = 0; o < 8; o++) {
        float whr[4], whi[4];
        #pragma unroll
        for (int cc = 0; cc < 4; cc++) {
            int base  = (o * 4 + cc) * (NN2 * 2);
            float w1r = w[base + wbase],  w1i = w[base + wbase + 1];
            float w2r = w[base + wmbase], w2i = w[base + wmbase + 1];
            whr[cc] = s * (w1r + w2r);
            whi[cc] = s * (w1i - w2i);
        }
        #pragma unroll
        for (int b = 0; b < 4; b++) {
            float ar = 0.f, ai = 0.f;
            #pragma unroll
            for (int cc = 0; cc < 4; cc++) {
                float xr = fr[b*4+cc], xi = fi[b*4+cc];
                ar += xr * whr[cc] - xi * whi[cc];
                ai += xr * whi[cc] + xi * whr[cc];
            }
            int idx = (b * 8 + o) * (HH*LD) + hidx;
            __nv_bfloat16 h, l;
            split_bf16(ar, h, l);  g_Hrh[idx] = h;  g_Hrl[idx] = l;
            split_bf16(ai, h, l);  g_Hih[idx] = h;  g_Hil[idx] = l;
        }
    }
}

// ---------------------------------------------------------------------------
// inv_u via mma.sync: C[256, 512] = A[256, 3072] * B[512, 3072]^T per batch.
// K = 6 blocks of 512: {Hrh*Brh, Hih*Bih, Hrl*Brh, Hil*Bih, Hrh*Brl, Hih*Bil}.
// N cols 0..255 -> Ur, 256..511 -> Ui. CTA tile 128x128, 8 warps (2x4) of 64x32.
// K-chunk 64 bf16 (128B), smem row stride 144B (conflict-free ldmatrix).
// grid (4 ntile, 2 mtile, 32 batch), 256 threads.
#define KC 64
#define ROWB 144
#define TILEB (128 * ROWB)          // 18432
#define BUFB  (2 * TILEB)           // 36864 per buffer (A + B)
__global__ void __launch_bounds__(256) k_inv_u_mma() {
    extern __shared__ char dyn_smem[];
    char* base = (char*)(((uintptr_t)dyn_smem + 127) & ~(uintptr_t)127);
    const uint32_t tiles = smem_u32(base);

    const int t = threadIdx.x, lane = t & 31, wid = t >> 5;
    const int wm = wid >> 2, wn = wid & 3;          // warp 64-row half, 32-col quarter
    const int ntile = blockIdx.x, mtile = blockIdx.y, batch = blockIdx.z;

    const size_t hB = (size_t)batch * (HH * LD);
    const __nv_bfloat16* Ablk[6] = { g_Hrh + hB, g_Hih + hB, g_Hrl + hB,
                                     g_Hil + hB, g_Hrh + hB, g_Hih + hB };
    const __nv_bfloat16* Bblk[6] = { g_Brh, g_Bih, g_Brh, g_Bih, g_Brl, g_Bil };

    // global loads: thread -> row t>>1 (0..127), half t&1 (64B of the 128B row)
    const int grow = t >> 1, ghalf = t & 1;
    const size_t aGbase = (size_t)(mtile*128 + grow) * LD + ghalf*32;
    const size_t bGbase = (size_t)(ntile*128 + grow) * LD + ghalf*32;
    const uint32_t sOff = (uint32_t)(grow * ROWB + ghalf * 64);

    // ldmatrix per-thread offsets
    const uint32_t aFrag = (uint32_t)((wm*64 + (lane & 15)) * ROWB + (lane >> 4) * 16);
    const uint32_t bFrag = (uint32_t)((wn*32 + (lane & 7)) * ROWB + ((lane >> 3) & 1) * 16);

    float acc[4][4][4];
    #pragma unroll
    for (int i = 0; i < 4; i++)
        #pragma unroll
        for (int j = 0; j < 4; j++)
            #pragma unroll
            for (int q = 0; q < 4; q++) acc[i][j][q] = 0.f;

    uint4 av[4], bv[4];
    {   // prefetch chunk 0
        const __nv_bfloat16* Ag = Ablk[0] + aGbase;
        const __nv_bfloat16* Bg = Bblk[0] + bGbase;
        #pragma unroll
        for (int i = 0; i < 4; i++) {
            av[i] = *(const uint4*)(Ag + i*8);
            bv[i] = *(const uint4*)(Bg + i*8);
        }
    }

    for (int c = 0; c < 48; c++) {
        const int buf = c & 1;
        char* aT = base + buf * BUFB;
        char* bT = aT + TILEB;
        __syncthreads();
        #pragma unroll
        for (int i = 0; i < 4; i++) {
            *(uint4*)(aT + sOff + i*16) = av[i];
            *(uint4*)(bT + sOff + i*16) = bv[i];
        }
        __syncthreads();
        if (c + 1 < 48) {
            const int blk = (c + 1) >> 3;
            const int k0  = ((c + 1) & 7) * KC;
            const __nv_bfloat16* Ag = Ablk[blk] + aGbase + k0;
            const __nv_bfloat16* Bg = Bblk[blk] + bGbase + k0;
            #pragma unroll
            for (int i = 0; i < 4; i++) {
                av[i] = *(const uint4*)(Ag + i*8);
                bv[i] = *(const uint4*)(Bg + i*8);
            }
        }
        const uint32_t aBase = tiles + buf * BUFB + aFrag;
        const uint32_t bBase = tiles + buf * BUFB + TILEB + bFrag;
        #pragma unroll
        for (int kk = 0; kk < 4; kk++) {
            uint32_t af[4][4], bf[4][2];
            #pragma unroll
            for (int mi = 0; mi < 4; mi++)
                ldsm_x4(af[mi][0], af[mi][1], af[mi][2], af[mi][3],
                        aBase + mi * (16 * ROWB) + kk * 32);
            #pragma unroll
            for (int ni = 0; ni < 4; ni++)
                ldsm_x2(bf[ni][0], bf[ni][1], bBase + ni * (8 * ROWB) + kk * 32);
            #pragma unroll
            for (int mi = 0; mi < 4; mi++)
                #pragma unroll
                for (int ni = 0; ni < 4; ni++)
                    mma_bf16(acc[mi][ni], af[mi], bf[ni]);
        }
    }

    // epilogue: write fp32 to Ur (ntile 0,1) or Ui (ntile 2,3)
    const int group = lane >> 2, tid4 = lane & 3;
    float* U = ((ntile < 2) ? g_Ur : g_Ui) + (size_t)batch * (HH*HH);
    const int colBase = (ntile & 1) * 128 + wn*32 + tid4*2;
    const int rowBase = mtile*128 + wm*64 + group;
    #pragma unroll
    for (int mi = 0; mi < 4; mi++) {
        #pragma unroll
        for (int ni = 0; ni < 4; ni++) {
            int m = rowBase + mi*16;
            int cn = colBase + ni*8;
            *(float2*)&U[(size_t)m * HH + cn]       = make_float2(acc[mi][ni][0], acc[mi][ni][1]);
            *(float2*)&U[(size_t)(m + 8) * HH + cn] = make_float2(acc[mi][ni][2], acc[mi][ni][3]);
        }
    }
}

// ---------------------------------------------------------------------------
// out[n1][n2] = scale * sum_{k1<256} (Tr[127+n1][k1]*Ur[k1][n2] + Ti*Ui) + bias
__global__ void __launch_bounds__(256, 2) k_out(const float* __restrict__ bias,
                                               float* __restrict__ out) {
    const int batch = blockIdx.z;
    const int m0 = blockIdx.y * 128;
    const int n0 = blockIdx.x * 64;
    const float* __restrict__ Br = g_Ur + batch * (HH * HH);
    const float* __restrict__ Bi = g_Ui + batch * (HH * HH);
    float* C = out + batch * (HH * HH);
    const float scale = 1.0f / ((float)NF * (float)NF);
    const float bv = bias[batch & 7];

    __shared__ __align__(16) float sAr[8][128], sAi[8][128];
    __shared__ __align__(16) float sBr[8][128], sBi[8][128];

    const int t = threadIdx.x;
    const int tx = t & 15, ty = t >> 4;
    const int arow = t >> 1, akp = (t & 1) * 4;
    const int bk = t >> 4,  bn4 = (t & 15) * 4;

    u64 cc[4][4];
    #pragma unroll
    for (int i = 0; i < 4; i++)
        #pragma unroll
        for (int j = 0; j < 4; j++) cc[i][j] = 0ull;

    float4 va_r, va_i, vb_r, vb_i;
    va_r = *(const float4*)&g_Tr[(CROP0 + m0 + arow) * LD + akp];
    va_i = *(const float4*)&g_Ti[(CROP0 + m0 + arow) * LD + akp];
    if (t < 128) {
        vb_r = *(const float4*)&Br[bk * HH + n0 + bn4];
        vb_i = *(const float4*)&Bi[bk * HH + n0 + bn4];
    }
    const int NCH = HH / 8;
    for (int c = 0; c < NCH; c++) {
        __syncthreads();
        sAr[akp+0][arow] = va_r.x; sAr[akp+1][arow] = va_r.y;
        sAr[akp+2][arow] = va_r.z; sAr[akp+3][arow] = va_r.w;
        sAi[akp+0][arow] = va_i.x; sAi[akp+1][arow] = va_i.y;
        sAi[akp+2][arow] = va_i.z; sAi[akp+3][arow] = va_i.w;
        if (t < 128) {
            *(u64*)&sBr[bk][2*(bn4+0)] = pack2(vb_r.x, vb_r.x);
            *(u64*)&sBr[bk][2*(bn4+1)] = pack2(vb_r.y, vb_r.y);
            *(u64*)&sBr[bk][2*(bn4+2)] = pack2(vb_r.z, vb_r.z);
            *(u64*)&sBr[bk][2*(bn4+3)] = pack2(vb_r.w, vb_r.w);
            *(u64*)&sBi[bk][2*(bn4+0)] = pack2(vb_i.x, vb_i.x);
            *(u64*)&sBi[bk][2*(bn4+1)] = pack2(vb_i.y, vb_i.y);
            *(u64*)&sBi[bk][2*(bn4+2)] = pack2(vb_i.z, vb_i.z);
            *(u64*)&sBi[bk][2*(bn4+3)] = pack2(vb_i.w, vb_i.w);
        }
        __syncthreads();
        if (c + 1 < NCH) {
            int k0 = (c + 1) * 8;
            va_r = *(const float4*)&g_Tr[(CROP0 + m0 + arow) * LD + k0 + akp];
            va_i = *(const float4*)&g_Ti[(CROP0 + m0 + arow) * LD + k0 + akp];
            if (t < 128) {
                vb_r = *(const float4*)&Br[(k0 + bk) * HH + n0 + bn4];
                vb_i = *(const float4*)&Bi[(k0 + bk) * HH + n0 + bn4];
            }
        }
        #pragma unroll
        for (int k = 0; k < 8; k++) {
            ulonglong2 A0 = *(const ulonglong2*)&sAr[k][ty*8];
            ulonglong2 A1 = *(const ulonglong2*)&sAr[k][ty*8+4];
            ulonglong2 E0 = *(const ulonglong2*)&sAi[k][ty*8];
            ulonglong2 E1 = *(const ulonglong2*)&sAi[k][ty*8+4];
            u64 ar[4] = {A0.x, A0.y, A1.x, A1.y};
            u64 ai_[4] = {E0.x, E0.y, E1.x, E1.y};
            #pragma unroll
            for (int j = 0; j < 4; j++) {
                int jj = 2 * (tx*4 + j);
                u64 br = *(const u64*)&sBr[k][jj];
                u64 bi = *(const u64*)&sBi[k][jj];
                #pragma unroll
                for (int i2 = 0; i2 < 4; i2++) {
                    fma2(cc[i2][j], ar[i2], br);
                    fma2(cc[i2][j], ai_[i2], bi);
                }
            }
        }
    }
    #pragma unroll
    for (int i2 = 0; i2 < 4; i2++) {
        float lo[4], hi[4];
        int row = m0 + ty * 8 + 2 * i2;
        #pragma unroll
        for (int j = 0; j < 4; j++) unpack2(cc[i2][j], lo[j], hi[j]);
        *(float4*)&C[row * HH + n0 + tx*4] =
            make_float4(lo[0]*scale+bv, lo[1]*scale+bv, lo[2]*scale+bv, lo[3]*scale+bv);
        *(float4*)&C[(row+1) * HH + n0 + tx*4] =
            make_float4(hi[0]*scale+bv, hi[1]*scale+bv, hi[2]*scale+bv, hi[3]*scale+bv);
    }
}

// ---------------------------------------------------------------------------
extern "C" void kernel_launch(void* const* d_in, const int* in_sizes, int n_in,
                              void* d_out, int out_size) {
    const float* im   = (const float*)d_in[0];   // (4,4,256,256)
    const float* wgt  = (const float*)d_in[1];   // (8,4,511,511,2)
    const float* bias = (const float*)d_in[2];   // (8,1,1)
    float* out = (float*)d_out;                  // (4,8,256,256)

    static int smem_set = 0;
    if (!smem_set) {
        cudaFuncSetAttribute(k_inv_u_mma, cudaFuncAttributeMaxDynamicSharedMemorySize,
                             2 * BUFB + 128);
        smem_set = 1;
    }

    k_twiddle  <<<(LD * LD) / 256, 256>>>();
    k_prep_binv<<<(LD * LD) / 256, 256>>>();
    k_fwd_cols <<<dim3(4, 2, 16), 256>>>(im);
    k_fwd_rows <<<dim3(8, 2, 16), 256>>>();
    k_einsum_h <<<dim3(2, 256),   256>>>(wgt);
    k_inv_u_mma<<<dim3(4, 2, 32), 256, 2 * BUFB + 128>>>();
    k_out      <<<dim3(4, 2, 32), 256>>>(bias, out);
}

// round 9
// speedup vs baseline: 4.0720x; 1.4587x over previous
#include <cuda_runtime.h>
#include <cuda_bf16.h>
#include <math_constants.h>
#include <cstdint>

// FourierConv2D via DFT matmuls. All large GEMMs on mma.sync bf16
// split-precision (hi/lo, lo*lo dropped). fwd_cols stays scalar FFMA2 but
// emits split-bf16 T1; inv_u emits transposed split-bf16 U for k_out.

#define NF 511
#define LD 512
#define HH 256
#define CROP0 127
#define NN2 (NF*NF)

typedef unsigned long long u64;

// ---- scratch (device globals) ----
__device__ float g_Tr[LD*LD], g_Ti[LD*LD];
// split-bf16 T1 (fwd_cols output) [bc][k1][n2]
__device__ __nv_bfloat16 g_T1rh[16*HH*HH], g_T1rl[16*HH*HH];
__device__ __nv_bfloat16 g_T1ih[16*HH*HH], g_T1il[16*HH*HH];
// fwd_rows B operands: P=[Tr;Ti], Q=[-Ti;Tr], rows n<1024, k<256
__device__ __nv_bfloat16 g_Ph[1024*HH], g_Pl[1024*HH];
__device__ __nv_bfloat16 g_Qh[1024*HH], g_Ql[1024*HH];
// split twiddle (k_out A operand): rows 0..511, cols 0..255
__device__ __nv_bfloat16 g_sTrh[LD*HH], g_sTrl[LD*HH];
__device__ __nv_bfloat16 g_sTih[LD*HH], g_sTil[LD*HH];
// F (fwd_rows output, fp32) [bc][k1<256][k2], col 511 = 0
__device__ float g_Fr[16*HH*LD], g_Fi[16*HH*LD];
// split-bf16 H (einsum output) and B (inv_u operand)
__device__ __nv_bfloat16 g_Hrh[32*HH*LD], g_Hrl[32*HH*LD];
__device__ __nv_bfloat16 g_Hih[32*HH*LD], g_Hil[32*HH*LD];
__device__ __nv_bfloat16 g_Brh[LD*LD], g_Bih[LD*LD], g_Brl[LD*LD], g_Bil[LD*LD];
// transposed split-bf16 U (inv_u output) [bo][n2][k1]
__device__ __nv_bfloat16 g_UrTh[32*HH*HH], g_UrTl[32*HH*HH];
__device__ __nv_bfloat16 g_UiTh[32*HH*HH], g_UiTl[32*HH*HH];

// ---- f32x2 helpers ----
__device__ __forceinline__ void fma2(u64 &d, u64 a, u64 b) {
    asm("fma.rn.f32x2 %0, %1, %2, %0;" : "+l"(d) : "l"(a), "l"(b));
}
__device__ __forceinline__ u64 pack2(float lo, float hi) {
    u64 r; asm("mov.b64 %0, {%1,%2};" : "=l"(r) : "f"(lo), "f"(hi)); return r;
}
__device__ __forceinline__ void unpack2(u64 v, float &lo, float &hi) {
    asm("mov.b64 {%0,%1}, %2;" : "=f"(lo), "=f"(hi) : "l"(v));
}
__device__ __forceinline__ void split_bf16(float v, __nv_bfloat16 &h, __nv_bfloat16 &l) {
    h = __float2bfloat16(v);
    l = __float2bfloat16(v - __bfloat162float(h));
}
__device__ __forceinline__ void split_store(__nv_bfloat16* H, __nv_bfloat16* L,
                                            size_t idx, float v) {
    __nv_bfloat16 h, l; split_bf16(v, h, l); H[idx] = h; L[idx] = l;
}
// split 4 consecutive values, one 8B store per array
__device__ __forceinline__ void split4_store(__nv_bfloat16* H, __nv_bfloat16* L,
                                             size_t idx, float v0, float v1,
                                             float v2, float v3) {
    __nv_bfloat16 h, l; ushort4 hs, ls;
    split_bf16(v0, h, l); hs.x = __bfloat16_as_ushort(h); ls.x = __bfloat16_as_ushort(l);
    split_bf16(v1, h, l); hs.y = __bfloat16_as_ushort(h); ls.y = __bfloat16_as_ushort(l);
    split_bf16(v2, h, l); hs.z = __bfloat16_as_ushort(h); ls.z = __bfloat16_as_ushort(l);
    split_bf16(v3, h, l); hs.w = __bfloat16_as_ushort(h); ls.w = __bfloat16_as_ushort(l);
    *(ushort4*)(H + idx) = hs;
    *(ushort4*)(L + idx) = ls;
}

// ---- mma.sync helpers ----
__device__ __forceinline__ uint32_t smem_u32(const void* p) {
    uint32_t a;
    asm("{ .reg .u64 t; cvta.to.shared.u64 t, %1; cvt.u32.u64 %0, t; }" : "=r"(a) : "l"(p));
    return a;
}
__device__ __forceinline__ void ldsm_x4(uint32_t &r0, uint32_t &r1, uint32_t &r2, uint32_t &r3,
                                        uint32_t addr) {
    asm volatile("ldmatrix.sync.aligned.m8n8.x4.shared.b16 {%0,%1,%2,%3}, [%4];"
                 : "=r"(r0), "=r"(r1), "=r"(r2), "=r"(r3) : "r"(addr));
}
__device__ __forceinline__ void ldsm_x2(uint32_t &r0, uint32_t &r1, uint32_t addr) {
    asm volatile("ldmatrix.sync.aligned.m8n8.x2.shared.b16 {%0,%1}, [%2];"
                 : "=r"(r0), "=r"(r1) : "r"(addr));
}
__device__ __forceinline__ void mma_bf16(float* c, const uint32_t* a, const uint32_t* b) {
    asm volatile("mma.sync.aligned.m16n8k16.row.col.f32.bf16.bf16.f32 "
                 "{%0,%1,%2,%3}, {%4,%5,%6,%7}, {%8,%9}, {%0,%1,%2,%3};"
                 : "+f"(c[0]), "+f"(c[1]), "+f"(c[2]), "+f"(c[3])
                 : "r"(a[0]), "r"(a[1]), "r"(a[2]), "r"(a[3]), "r"(b[0]), "r"(b[1]));
}

#define KC 64
#define ROWB 144
#define TILEB (128 * ROWB)
#define BUFB  (2 * TILEB)
#define MMA_SMEM (2 * BUFB + 128)

// ---------------------------------------------------------------------------
__global__ void __launch_bounds__(256) k_twiddle() {
    int p = blockIdx.x * 256 + threadIdx.x;
    int a = p >> 9, b = p & 511;
    float cr = 0.f, ci = 0.f;
    if (a < NF && b < NF) {
        int r = (a * b) % NF;
        float ang = (-2.0f * CUDART_PI_F / (float)NF) * (float)r;
        sincosf(ang, &ci, &cr);
    }
    g_Tr[p] = cr;
    g_Ti[p] = ci;
}

// inv_u B operand: rows<256 -> (Tr,Ti)@row 127+n ; rows>=256 -> (-Ti,Tr).
__global__ void __launch_bounds__(256) k_prep_binv() {
    int p = blockIdx.x * 256 + threadIdx.x;    // 512*512
    int n = p >> 9, k = p & 511;
    float br, bi;
    if (n < 256) { br = g_Tr[(CROP0+n)*LD + k]; bi = g_Ti[(CROP0+n)*LD + k]; }
    else { int m = n - 256; br = -g_Ti[(CROP0+m)*LD + k]; bi = g_Tr[(CROP0+m)*LD + k]; }
    split_store(g_Brh, g_Brl, p, br);
    split_store(g_Bih, g_Bil, p, bi);
}

// split twiddle [512][256] (k_out A) + P/Q [1024][256] (fwd_rows B)
__global__ void __launch_bounds__(256) k_prep_pq() {
    int p = blockIdx.x * 256 + threadIdx.x;    // 1024*256
    int n = p >> 8, k = p & 255;
    if (n < 512) {
        float tr = g_Tr[n*LD + k], ti = g_Ti[n*LD + k];
        split_store(g_sTrh, g_sTrl, p, tr);
        split_store(g_sTih, g_sTil, p, ti);
        split_store(g_Ph, g_Pl, p, tr);
        split_store(g_Qh, g_Ql, p, -ti);
    } else {
        int m = n - 512;
        float tr = g_Tr[m*LD + k], ti = g_Ti[m*LD + k];
        split_store(g_Ph, g_Pl, p, ti);
        split_store(g_Qh, g_Ql, p, tr);
    }
}

// ---------------------------------------------------------------------------
// G1: T1[k1][n2] = sum_{n1<256} T[k1][n1] * x[n1][n2]; scalar FFMA2,
// epilogue emits split-bf16 T1. grid (4, 2, 16)
__global__ void __launch_bounds__(256, 2) k_fwd_cols(const float* __restrict__ x) {
    const int batch = blockIdx.z;
    const int m0 = blockIdx.y * 128;
    const int n0 = blockIdx.x * 64;
    const float* __restrict__ B = x + batch * (HH * HH);
    const size_t obase = (size_t)batch * (HH * HH);

    __shared__ __align__(16) float sAr[8][128], sAi[8][128], sB[8][128];
    const int t = threadIdx.x;
    const int tx = t & 15, ty = t >> 4;
    const int arow = t >> 1, akp = (t & 1) * 4;
    const int bk = t >> 4,  bn4 = (t & 15) * 4;

    u64 cr[4][4], ci[4][4];
    #pragma unroll
    for (int i = 0; i < 4; i++)
        #pragma unroll
        for (int j = 0; j < 4; j++) { cr[i][j] = 0ull; ci[i][j] = 0ull; }

    float4 va_r, va_i, vb;
    va_r = *(const float4*)&g_Tr[(m0 + arow) * LD + akp];
    va_i = *(const float4*)&g_Ti[(m0 + arow) * LD + akp];
    if (t < 128) vb = *(const float4*)&B[bk * HH + n0 + bn4];

    const int NCH = HH / 8;
    for (int c = 0; c < NCH; c++) {
        __syncthreads();
        sAr[akp+0][arow] = va_r.x; sAr[akp+1][arow] = va_r.y;
        sAr[akp+2][arow] = va_r.z; sAr[akp+3][arow] = va_r.w;
        sAi[akp+0][arow] = va_i.x; sAi[akp+1][arow] = va_i.y;
        sAi[akp+2][arow] = va_i.z; sAi[akp+3][arow] = va_i.w;
        if (t < 128) {
            *(u64*)&sB[bk][2*(bn4+0)] = pack2(vb.x, vb.x);
            *(u64*)&sB[bk][2*(bn4+1)] = pack2(vb.y, vb.y);
            *(u64*)&sB[bk][2*(bn4+2)] = pack2(vb.z, vb.z);
            *(u64*)&sB[bk][2*(bn4+3)] = pack2(vb.w, vb.w);
        }
        __syncthreads();
        if (c + 1 < NCH) {
            int k0 = (c + 1) * 8;
            va_r = *(const float4*)&g_Tr[(m0 + arow) * LD + k0 + akp];
            va_i = *(const float4*)&g_Ti[(m0 + arow) * LD + k0 + akp];
            if (t < 128) vb = *(const float4*)&B[(k0 + bk) * HH + n0 + bn4];
        }
        #pragma unroll
        for (int k = 0; k < 8; k++) {
            ulonglong2 A0 = *(const ulonglong2*)&sAr[k][ty*8];
            ulonglong2 A1 = *(const ulonglong2*)&sAr[k][ty*8+4];
            ulonglong2 E0 = *(const ulonglong2*)&sAi[k][ty*8];
            ulonglong2 E1 = *(const ulonglong2*)&sAi[k][ty*8+4];
            u64 ar[4] = {A0.x, A0.y, A1.x, A1.y};
            u64 ai_[4] = {E0.x, E0.y, E1.x, E1.y};
            #pragma unroll
            for (int j = 0; j < 4; j++) {
                u64 bb = *(const u64*)&sB[k][2*(tx*4+j)];
                #pragma unroll
                for (int i2 = 0; i2 < 4; i2++) {
                    fma2(cr[i2][j], ar[i2], bb);
                    fma2(ci[i2][j], ai_[i2], bb);
                }
            }
        }
    }
    #pragma unroll
    for (int i2 = 0; i2 < 4; i2++) {
        float lo[4], hi[4];
        int row = m0 + ty * 8 + 2 * i2;
        size_t idx0 = obase + (size_t)row * HH + n0 + tx*4;
        #pragma unroll
        for (int j = 0; j < 4; j++) unpack2(cr[i2][j], lo[j], hi[j]);
        split4_store(g_T1rh, g_T1rl, idx0,      lo[0], lo[1], lo[2], lo[3]);
        split4_store(g_T1rh, g_T1rl, idx0 + HH, hi[0], hi[1], hi[2], hi[3]);
        #pragma unroll
        for (int j = 0; j < 4; j++) unpack2(ci[i2][j], lo[j], hi[j]);
        split4_store(g_T1ih, g_T1il, idx0,      lo[0], lo[1], lo[2], lo[3]);
        split4_store(g_T1ih, g_T1il, idx0 + HH, hi[0], hi[1], hi[2], hi[3]);
    }
}

// ---------------------------------------------------------------------------
// fwd_rows via mma: C[256, 1024] = A[256, 1536]*B[1024, 1536]^T per bc batch.
// K-blocks: {(T1rh,Ph),(T1ih,Qh),(T1rl,Ph),(T1il,Qh),(T1rh,Pl),(T1ih,Ql)}.
// N cols 0..511 -> Fr, 512..1023 -> Fi (fp32 out, stride LD).
// grid (8 ntile, 2 mtile, 16 batch), 256 threads.
__global__ void __launch_bounds__(256) k_fwd_rows_mma() {
    extern __shared__ char dyn_smem[];
    char* base = (char*)(((uintptr_t)dyn_smem + 127) & ~(uintptr_t)127);
    const uint32_t tiles = smem_u32(base);

    const int t = threadIdx.x, lane = t & 31, wid = t >> 5;
    const int wm = wid >> 2, wn = wid & 3;
    const int ntile = blockIdx.x, mtile = blockIdx.y, batch = blockIdx.z;

    const size_t aB = (size_t)batch * (HH * HH);
    const __nv_bfloat16* Ablk[6] = { g_T1rh + aB, g_T1ih + aB, g_T1rl + aB,
                                     g_T1il + aB, g_T1rh + aB, g_T1ih + aB };
    const __nv_bfloat16* Bblk[6] = { g_Ph, g_Qh, g_Ph, g_Qh, g_Pl, g_Ql };

    const int grow = t >> 1, ghalf = t & 1;
    const size_t aGbase = (size_t)(mtile*128 + grow) * HH + ghalf*32;
    const size_t bGbase = (size_t)(ntile*128 + grow) * HH + ghalf*32;
    const uint32_t sOff = (uint32_t)(grow * ROWB + ghalf * 64);
    const uint32_t aFrag = (uint32_t)((wm*64 + (lane & 15)) * ROWB + (lane >> 4) * 16);
    const uint32_t bFrag = (uint32_t)((wn*32 + (lane & 7)) * ROWB + ((lane >> 3) & 1) * 16);

    float acc[4][4][4];
    #pragma unroll
    for (int i = 0; i < 4; i++)
        #pragma unroll
        for (int j = 0; j < 4; j++)
            #pragma unroll
            for (int q = 0; q < 4; q++) acc[i][j][q] = 0.f;

    uint4 av[4], bv[4];
    {
        const __nv_bfloat16* Ag = Ablk[0] + aGbase;
        const __nv_bfloat16* Bg = Bblk[0] + bGbase;
        #pragma unroll
        for (int i = 0; i < 4; i++) {
            av[i] = *(const uint4*)(Ag + i*8);
            bv[i] = *(const uint4*)(Bg + i*8);
        }
    }

    for (int c = 0; c < 24; c++) {
        const int buf = c & 1;
        char* aT = base + buf * BUFB;
        char* bT = aT + TILEB;
        __syncthreads();
        #pragma unroll
        for (int i = 0; i < 4; i++) {
            *(uint4*)(aT + sOff + i*16) = av[i];
            *(uint4*)(bT + sOff + i*16) = bv[i];
        }
        __syncthreads();
        if (c + 1 < 24) {
            const int blk = (c + 1) >> 2;
            const int k0  = ((c + 1) & 3) * KC;
            const __nv_bfloat16* Ag = Ablk[blk] + aGbase + k0;
            const __nv_bfloat16* Bg = Bblk[blk] + bGbase + k0;
            #pragma unroll
            for (int i = 0; i < 4; i++) {
                av[i] = *(const uint4*)(Ag + i*8);
                bv[i] = *(const uint4*)(Bg + i*8);
            }
        }
        const uint32_t aBase = tiles + buf * BUFB + aFrag;
        const uint32_t bBase = tiles + buf * BUFB + TILEB + bFrag;
        #pragma unroll
        for (int kk = 0; kk < 4; kk++) {
            uint32_t af[4][4], bf[4][2];
            #pragma unroll
            for (int mi = 0; mi < 4; mi++)
                ldsm_x4(af[mi][0], af[mi][1], af[mi][2], af[mi][3],
                        aBase + mi * (16 * ROWB) + kk * 32);
            #pragma unroll
            for (int ni = 0; ni < 4; ni++)
                ldsm_x2(bf[ni][0], bf[ni][1], bBase + ni * (8 * ROWB) + kk * 32);
            #pragma unroll
            for (int mi = 0; mi < 4; mi++)
                #pragma unroll
                for (int ni = 0; ni < 4; ni++)
                    mma_bf16(acc[mi][ni], af[mi], bf[ni]);
        }
    }

    const int group = lane >> 2, tid4 = lane & 3;
    float* F = ((ntile < 4) ? g_Fr : g_Fi) + (size_t)batch * (HH*LD);
    const int colBase = (ntile & 3) * 128 + wn*32 + tid4*2;
    const int rowBase = mtile*128 + wm*64 + group;
    #pragma unroll
    for (int mi = 0; mi < 4; mi++) {
        #pragma unroll
        for (int ni = 0; ni < 4; ni++) {
            int m = rowBase + mi*16;
            int cn = colBase + ni*8;
            *(float2*)&F[(size_t)m * LD + cn]       = make_float2(acc[mi][ni][0], acc[mi][ni][1]);
            *(float2*)&F[(size_t)(m + 8) * LD + cn] = make_float2(acc[mi][ni][2], acc[mi][ni][3]);
        }
    }
}

// ---------------------------------------------------------------------------
// Einsum with Hermitian weight projection; outputs split-bf16 H.
__global__ void __launch_bounds__(256) k_einsum_h(const float* __restrict__ w) {
    int k2 = blockIdx.x * 256 + threadIdx.x;       // 0..511
    int k1 = blockIdx.y;                           // 0..255
    if (k2 == 511) {
        #pragma unroll
        for (int bo = 0; bo < 32; bo++) {
            int idx = bo * (HH*LD) + k1 * LD + 511;
            g_Hrh[idx] = __float2bfloat16(0.f); g_Hrl[idx] = __float2bfloat16(0.f);
            g_Hih[idx] = __float2bfloat16(0.f); g_Hil[idx] = __float2bfloat16(0.f);
        }
        return;
    }
    float fr[16], fi[16];
    {
        int off = k1 * LD + k2;
        #pragma unroll
        for (int bc = 0; bc < 16; bc++) {
            fr[bc] = g_Fr[bc * (HH*LD) + off];
            fi[bc] = g_Fi[bc * (HH*LD) + off];
        }
    }
    const int m1 = (k1 == 0) ? 0 : (NF - k1);
    const int m2 = (k2 == 0) ? 0 : (NF - k2);
    const int wbase  = (k1 * NF + k2) * 2;
    const int wmbase = (m1 * NF + m2) * 2;
    const float s = (k1 == 0) ? 0.5f : 1.0f;
    const int hidx = k1 * LD + k2;
    #pragma unroll
    for (int o = 0; o < 8; o++) {
        float whr[4], whi[4];
        #pragma unroll
        for (int cc = 0; cc < 4; cc++) {
            int base  = (o * 4 + cc) * (NN2 * 2);
            float w1r = w[base + wbase],  w1i = w[base + wbase + 1];
            float w2r = w[base + wmbase], w2i = w[base + wmbase + 1];
            whr[cc] = s * (w1r + w2r);
            whi[cc] = s * (w1i - w2i);
        }
        #pragma unroll
        for (int b = 0; b < 4; b++) {
            float ar = 0.f, ai = 0.f;
            #pragma unroll
            for (int cc = 0; cc < 4; cc++) {
                float xr = fr[b*4+cc], xi = fi[b*4+cc];
                ar += xr * whr[cc] - xi * whi[cc];
                ai += xr * whi[cc] + xi * whr[cc];
            }
            int idx = (b * 8 + o) * (HH*LD) + hidx;
            split_store(g_Hrh, g_Hrl, idx, ar);
            split_store(g_Hih, g_Hil, idx, ai);
        }
    }
}

// ---------------------------------------------------------------------------
// inv_u via mma: C[256, 512] = A[256, 3072]*B[512, 3072]^T per bo batch.
// Epilogue writes TRANSPOSED split-bf16 U: UT[n2][k1].
// grid (4 ntile, 2 mtile, 32 batch), 256 threads.
__global__ void __launch_bounds__(256) k_inv_u_mma() {
    extern __shared__ char dyn_smem[];
    char* base = (char*)(((uintptr_t)dyn_smem + 127) & ~(uintptr_t)127);
    const uint32_t tiles = smem_u32(base);

    const int t = threadIdx.x, lane = t & 31, wid = t >> 5;
    const int wm = wid >> 2, wn = wid & 3;
    const int ntile = blockIdx.x, mtile = blockIdx.y, batch = blockIdx.z;

    const size_t hB = (size_t)batch * (HH * LD);
    const __nv_bfloat16* Ablk[6] = { g_Hrh + hB, g_Hih + hB, g_Hrl + hB,
                                     g_Hil + hB, g_Hrh + hB, g_Hih + hB };
    const __nv_bfloat16* Bblk[6] = { g_Brh, g_Bih, g_Brh, g_Bih, g_Brl, g_Bil };

    const int grow = t >> 1, ghalf = t & 1;
    const size_t aGbase = (size_t)(mtile*128 + grow) * LD + ghalf*32;
    const size_t bGbase = (size_t)(ntile*128 + grow) * LD + ghalf*32;
    const uint32_t sOff = (uint32_t)(grow * ROWB + ghalf * 64);
    const uint32_t aFrag = (uint32_t)((wm*64 + (lane & 15)) * ROWB + (lane >> 4) * 16);
    const uint32_t bFrag = (uint32_t)((wn*32 + (lane & 7)) * ROWB + ((lane >> 3) & 1) * 16);

    float acc[4][4][4];
    #pragma unroll
    for (int i = 0; i < 4; i++)
        #pragma unroll
        for (int j = 0; j < 4; j++)
            #pragma unroll
            for (int q = 0; q < 4; q++) acc[i][j][q] = 0.f;

    uint4 av[4], bv[4];
    {
        const __nv_bfloat16* Ag = Ablk[0] + aGbase;
        const __nv_bfloat16* Bg = Bblk[0] + bGbase;
        #pragma unroll
        for (int i = 0; i < 4; i++) {
            av[i] = *(const uint4*)(Ag + i*8);
            bv[i] = *(const uint4*)(Bg + i*8);
        }
    }

    for (int c = 0; c < 48; c++) {
        const int buf = c & 1;
        char* aT = base + buf * BUFB;
        char* bT = aT + TILEB;
        __syncthreads();
        #pragma unroll
        for (int i = 0; i < 4; i++) {
            *(uint4*)(aT + sOff + i*16) = av[i];
            *(uint4*)(bT + sOff + i*16) = bv[i];
        }
        __syncthreads();
        if (c + 1 < 48) {
            const int blk = (c + 1) >> 3;
            const int k0  = ((c + 1) & 7) * KC;
            const __nv_bfloat16* Ag = Ablk[blk] + aGbase + k0;
            const __nv_bfloat16* Bg = Bblk[blk] + bGbase + k0;
            #pragma unroll
            for (int i = 0; i < 4; i++) {
                av[i] = *(const uint4*)(Ag + i*8);
                bv[i] = *(const uint4*)(Bg + i*8);
            }
        }
        const uint32_t aBase = tiles + buf * BUFB + aFrag;
        const uint32_t bBase = tiles + buf * BUFB + TILEB + bFrag;
        #pragma unroll
        for (int kk = 0; kk < 4; kk++) {
            uint32_t af[4][4], bf[4][2];
            #pragma unroll
            for (int mi = 0; mi < 4; mi++)
                ldsm_x4(af[mi][0], af[mi][1], af[mi][2], af[mi][3],
                        aBase + mi * (16 * ROWB) + kk * 32);
            #pragma unroll
            for (int ni = 0; ni < 4; ni++)
                ldsm_x2(bf[ni][0], bf[ni][1], bBase + ni * (8 * ROWB) + kk * 32);
            #pragma unroll
            for (int mi = 0; mi < 4; mi++)
                #pragma unroll
                for (int ni = 0; ni < 4; ni++)
                    mma_bf16(acc[mi][ni], af[mi], bf[ni]);
        }
    }

    // epilogue: transposed split-bf16 stores: UT[n2][k1]
    const int group = lane >> 2, tid4 = lane & 3;
    const bool isR = (ntile < 2);
    __nv_bfloat16* Th = (isR ? g_UrTh : g_UiTh) + (size_t)batch * (HH*HH);
    __nv_bfloat16* Tl = (isR ? g_UrTl : g_UiTl) + (size_t)batch * (HH*HH);
    const int colBase = (ntile & 1) * 128 + wn*32 + tid4*2;
    const int rowBase = mtile*128 + wm*64 + group;
    #pragma unroll
    for (int mi = 0; mi < 4; mi++) {
        #pragma unroll
        for (int ni = 0; ni < 4; ni++) {
            int m = rowBase + mi*16;
            int cn = colBase + ni*8;
            split_store(Th, Tl, (size_t)cn * HH + m,           acc[mi][ni][0]);
            split_store(Th, Tl, (size_t)(cn + 1) * HH + m,     acc[mi][ni][1]);
            split_store(Th, Tl, (size_t)cn * HH + m + 8,       acc[mi][ni][2]);
            split_store(Th, Tl, (size_t)(cn + 1) * HH + m + 8, acc[mi][ni][3]);
        }
    }
}

// ---------------------------------------------------------------------------
// k_out via mma: out[n1][n2] = scale * (A[256,1536]*B[256,1536]^T) + bias,
// A from split crop twiddle (row offset 127), B = transposed split U.
// grid (2 ntile, 2 mtile, 32 batch), 256 threads.
__global__ void __launch_bounds__(256) k_out_mma(const float* __restrict__ bias,
                                                 float* __restrict__ out) {
    extern __shared__ char dyn_smem[];
    char* base = (char*)(((uintptr_t)dyn_smem + 127) & ~(uintptr_t)127);
    const uint32_t tiles = smem_u32(base);

    const int t = threadIdx.x, lane = t & 31, wid = t >> 5;
    const int wm = wid >> 2, wn = wid & 3;
    const int ntile = blockIdx.x, mtile = blockIdx.y, batch = blockIdx.z;
    const float scale = 1.0f / ((float)NF * (float)NF);
    const float bias_v = bias[batch & 7];

    const size_t uB = (size_t)batch * (HH * HH);
    const __nv_bfloat16* Ablk[6] = { g_sTrh, g_sTih, g_sTrl, g_sTil, g_sTrh, g_sTih };
    const __nv_bfloat16* Bblk[6] = { g_UrTh + uB, g_UiTh + uB, g_UrTh + uB,
                                     g_UiTh + uB, g_UrTl + uB, g_UiTl + uB };

    const int grow = t >> 1, ghalf = t & 1;
    const size_t aGbase = (size_t)(CROP0 + mtile*128 + grow) * HH + ghalf*32;
    const size_t bGbase = (size_t)(ntile*128 + grow) * HH + ghalf*32;
    const uint32_t sOff = (uint32_t)(grow * ROWB + ghalf * 64);
    const uint32_t aFrag = (uint32_t)((wm*64 + (lane & 15)) * ROWB + (lane >> 4) * 16);
    const uint32_t bFrag = (uint32_t)((wn*32 + (lane & 7)) * ROWB + ((lane >> 3) & 1) * 16);

    float acc[4][4][4];
    #pragma unroll
    for (int i = 0; i < 4; i++)
        #pragma unroll
        for (int j = 0; j < 4; j++)
            #pragma unroll
            for (int q = 0; q < 4; q++) acc[i][j][q] = 0.f;

    uint4 av[4], bv[4];
    {
        const __nv_bfloat16* Ag = Ablk[0] + aGbase;
        const __nv_bfloat16* Bg = Bblk[0] + bGbase;
        #pragma unroll
        for (int i = 0; i < 4; i++) {
            av[i] = *(const uint4*)(Ag + i*8);
            bv[i] = *(const uint4*)(Bg + i*8);
        }
    }

    for (int c = 0; c < 24; c++) {
        const int buf = c & 1;
        char* aT = base + buf * BUFB;
        char* bT = aT + TILEB;
        __syncthreads();
        #pragma unroll
        for (int i = 0; i < 4; i++) {
            *(uint4*)(aT + sOff + i*16) = av[i];
            *(uint4*)(bT + sOff + i*16) = bv[i];
        }
        __syncthreads();
        if (c + 1 < 24) {
            const int blk = (c + 1) >> 2;
            const int k0  = ((c + 1) & 3) * KC;
            const __nv_bfloat16* Ag = Ablk[blk] + aGbase + k0;
            const __nv_bfloat16* Bg = Bblk[blk] + bGbase + k0;
            #pragma unroll
            for (int i = 0; i < 4; i++) {
                av[i] = *(const uint4*)(Ag + i*8);
                bv[i] = *(const uint4*)(Bg + i*8);
            }
        }
        const uint32_t aBase = tiles + buf * BUFB + aFrag;
        const uint32_t bBase = tiles + buf * BUFB + TILEB + bFrag;
        #pragma unroll
        for (int kk = 0; kk < 4; kk++) {
            uint32_t af[4][4], bf[4][2];
            #pragma unroll
            for (int mi = 0; mi < 4; mi++)
                ldsm_x4(af[mi][0], af[mi][1], af[mi][2], af[mi][3],
                        aBase + mi * (16 * ROWB) + kk * 32);
            #pragma unroll
            for (int ni = 0; ni < 4; ni++)
                ldsm_x2(bf[ni][0], bf[ni][1], bBase + ni * (8 * ROWB) + kk * 32);
            #pragma unroll
            for (int mi = 0; mi < 4; mi++)
                #pragma unroll
                for (int ni = 0; ni < 4; ni++)
                    mma_bf16(acc[mi][ni], af[mi], bf[ni]);
        }
    }

    const int group = lane >> 2, tid4 = lane & 3;
    float* C = out + (size_t)batch * (HH*HH);
    const int colBase = ntile*128 + wn*32 + tid4*2;
    const int rowBase = mtile*128 + wm*64 + group;
    #pragma unroll
    for (int mi = 0; mi < 4; mi++) {
        #pragma unroll
        for (int ni = 0; ni < 4; ni++) {
            int m = rowBase + mi*16;
            int cn = colBase + ni*8;
            *(float2*)&C[(size_t)m * HH + cn] =
                make_float2(acc[mi][ni][0]*scale + bias_v, acc[mi][ni][1]*scale + bias_v);
            *(float2*)&C[(size_t)(m + 8) * HH + cn] =
                make_float2(acc[mi][ni][2]*scale + bias_v, acc[mi][ni][3]*scale + bias_v);
        }
    }
}

// ---------------------------------------------------------------------------
extern "C" void kernel_launch(void* const* d_in, const int* in_sizes, int n_in,
                              void* d_out, int out_size) {
    const float* im   = (const float*)d_in[0];   // (4,4,256,256)
    const float* wgt  = (const float*)d_in[1];   // (8,4,511,511,2)
    const float* bias = (const float*)d_in[2];   // (8,1,1)
    float* out = (float*)d_out;                  // (4,8,256,256)

    static int smem_set = 0;
    if (!smem_set) {
        cudaFuncSetAttribute(k_fwd_rows_mma, cudaFuncAttributeMaxDynamicSharedMemorySize, MMA_SMEM);
        cudaFuncSetAttribute(k_inv_u_mma,    cudaFuncAttributeMaxDynamicSharedMemorySize, MMA_SMEM);
        cudaFuncSetAttribute(k_out_mma,      cudaFuncAttributeMaxDynamicSharedMemorySize, MMA_SMEM);
        smem_set = 1;
    }

    k_twiddle     <<<(LD * LD) / 256, 256>>>();
    k_prep_binv   <<<(LD * LD) / 256, 256>>>();
    k_prep_pq     <<<(1024 * HH) / 256, 256>>>();
    k_fwd_cols    <<<dim3(4, 2, 16), 256>>>(im);
    k_fwd_rows_mma<<<dim3(8, 2, 16), 256, MMA_SMEM>>>();
    k_einsum_h    <<<dim3(2, 256),   256>>>(wgt);
    k_inv_u_mma   <<<dim3(4, 2, 32), 256, MMA_SMEM>>>();
    k_out_mma     <<<dim3(2, 2, 32), 256, MMA_SMEM>>>(bias, out);
}

// round 10
// speedup vs baseline: 4.3619x; 1.0712x over previous
#include <cuda_runtime.h>
#include <cuda_bf16.h>
#include <math_constants.h>
#include <cstdint>

// FourierConv2D via DFT matmuls. ALL four GEMMs on mma.sync bf16
// split-precision (hi/lo, lo*lo dropped). einsum scalar (DRAM-bound).

#define NF 511
#define LD 512
#define HH 256
#define CROP0 127
#define NN2 (NF*NF)

// ---- scratch (device globals) ----
__device__ float g_Tr[LD*LD], g_Ti[LD*LD];
// fwd_cols A operand: rows 0..255 = Tr[k1][n1<256], rows 256..511 = Ti
__device__ __nv_bfloat16 g_A1h[LD*HH], g_A1l[LD*HH];
// transposed split-bf16 input x: xT[bc][n2][n1]
__device__ __nv_bfloat16 g_xTh[16*HH*HH], g_xTl[16*HH*HH];
// split-bf16 T1 (fwd_cols output) [bc][k1][n2]
__device__ __nv_bfloat16 g_T1rh[16*HH*HH], g_T1rl[16*HH*HH];
__device__ __nv_bfloat16 g_T1ih[16*HH*HH], g_T1il[16*HH*HH];
// fwd_rows B operands: P=[Tr;Ti], Q=[-Ti;Tr], rows n<1024, k<256
__device__ __nv_bfloat16 g_Ph[1024*HH], g_Pl[1024*HH];
__device__ __nv_bfloat16 g_Qh[1024*HH], g_Ql[1024*HH];
// split twiddle (k_out A operand): rows 0..511, cols 0..255
__device__ __nv_bfloat16 g_sTrh[LD*HH], g_sTrl[LD*HH];
__device__ __nv_bfloat16 g_sTih[LD*HH], g_sTil[LD*HH];
// F (fwd_rows output, fp32) [bc][k1<256][k2], col 511 = 0
__device__ float g_Fr[16*HH*LD], g_Fi[16*HH*LD];
// split-bf16 H (einsum output) and B (inv_u operand)
__device__ __nv_bfloat16 g_Hrh[32*HH*LD], g_Hrl[32*HH*LD];
__device__ __nv_bfloat16 g_Hih[32*HH*LD], g_Hil[32*HH*LD];
__device__ __nv_bfloat16 g_Brh[LD*LD], g_Bih[LD*LD], g_Brl[LD*LD], g_Bil[LD*LD];
// transposed split-bf16 U (inv_u output) [bo][n2][k1]
__device__ __nv_bfloat16 g_UrTh[32*HH*HH], g_UrTl[32*HH*HH];
__device__ __nv_bfloat16 g_UiTh[32*HH*HH], g_UiTl[32*HH*HH];

// ---- split helpers ----
__device__ __forceinline__ void split_bf16(float v, __nv_bfloat16 &h, __nv_bfloat16 &l) {
    h = __float2bfloat16(v);
    l = __float2bfloat16(v - __bfloat162float(h));
}
__device__ __forceinline__ void split_store(__nv_bfloat16* H, __nv_bfloat16* L,
                                            size_t idx, float v) {
    __nv_bfloat16 h, l; split_bf16(v, h, l); H[idx] = h; L[idx] = l;
}

// ---- mma.sync helpers ----
__device__ __forceinline__ uint32_t smem_u32(const void* p) {
    uint32_t a;
    asm("{ .reg .u64 t; cvta.to.shared.u64 t, %1; cvt.u32.u64 %0, t; }" : "=r"(a) : "l"(p));
    return a;
}
__device__ __forceinline__ void ldsm_x4(uint32_t &r0, uint32_t &r1, uint32_t &r2, uint32_t &r3,
                                        uint32_t addr) {
    asm volatile("ldmatrix.sync.aligned.m8n8.x4.shared.b16 {%0,%1,%2,%3}, [%4];"
                 : "=r"(r0), "=r"(r1), "=r"(r2), "=r"(r3) : "r"(addr));
}
__device__ __forceinline__ void ldsm_x2(uint32_t &r0, uint32_t &r1, uint32_t addr) {
    asm volatile("ldmatrix.sync.aligned.m8n8.x2.shared.b16 {%0,%1}, [%2];"
                 : "=r"(r0), "=r"(r1) : "r"(addr));
}
__device__ __forceinline__ void mma_bf16(float* c, const uint32_t* a, const uint32_t* b) {
    asm volatile("mma.sync.aligned.m16n8k16.row.col.f32.bf16.bf16.f32 "
                 "{%0,%1,%2,%3}, {%4,%5,%6,%7}, {%8,%9}, {%0,%1,%2,%3};"
                 : "+f"(c[0]), "+f"(c[1]), "+f"(c[2]), "+f"(c[3])
                 : "r"(a[0]), "r"(a[1]), "r"(a[2]), "r"(a[3]), "r"(b[0]), "r"(b[1]));
}

#define KC 64
#define ROWB 144
#define TILEB (128 * ROWB)
#define BUFB  (2 * TILEB)
#define MMA_SMEM (2 * BUFB + 128)

// Shared GEMM mainloop body as a macro-free pattern is repeated per kernel
// (NCHUNK varies; epilogues differ).

// ---------------------------------------------------------------------------
__global__ void __launch_bounds__(256) k_twiddle() {
    int p = blockIdx.x * 256 + threadIdx.x;
    int a = p >> 9, b = p & 511;
    float cr = 0.f, ci = 0.f;
    if (a < NF && b < NF) {
        int r = (a * b) % NF;
        float ang = (-2.0f * CUDART_PI_F / (float)NF) * (float)r;
        sincosf(ang, &ci, &cr);
    }
    g_Tr[p] = cr;
    g_Ti[p] = ci;
}

// inv_u B operand: rows<256 -> (Tr,Ti)@row 127+n ; rows>=256 -> (-Ti,Tr).
__global__ void __launch_bounds__(256) k_prep_binv() {
    int p = blockIdx.x * 256 + threadIdx.x;    // 512*512
    int n = p >> 9, k = p & 511;
    float br, bi;
    if (n < 256) { br = g_Tr[(CROP0+n)*LD + k]; bi = g_Ti[(CROP0+n)*LD + k]; }
    else { int m = n - 256; br = -g_Ti[(CROP0+m)*LD + k]; bi = g_Tr[(CROP0+m)*LD + k]; }
    split_store(g_Brh, g_Brl, p, br);
    split_store(g_Bih, g_Bil, p, bi);
}

// split twiddle [512][256] (k_out A) + P/Q [1024][256] (fwd_rows B)
// + A1 [512][256] (fwd_cols A)
__global__ void __launch_bounds__(256) k_prep_pq() {
    int p = blockIdx.x * 256 + threadIdx.x;    // 1024*256
    int n = p >> 8, k = p & 255;
    if (n < 512) {
        float tr = g_Tr[n*LD + k], ti = g_Ti[n*LD + k];
        split_store(g_sTrh, g_sTrl, p, tr);
        split_store(g_sTih, g_sTil, p, ti);
        split_store(g_Ph, g_Pl, p, tr);
        split_store(g_Qh, g_Ql, p, -ti);
        if (n < 256) split_store(g_A1h, g_A1l, p, tr);
        else         split_store(g_A1h, g_A1l, p, g_Ti[(n-256)*LD + k]);
    } else {
        int m = n - 512;
        float tr = g_Tr[m*LD + k], ti = g_Ti[m*LD + k];
        split_store(g_Ph, g_Pl, p, ti);
        split_store(g_Qh, g_Ql, p, tr);
    }
}

// transpose + split input x: xT[bc][n2][n1] = x[bc][n1][n2]
// grid (8, 8, 16), block (32, 8)
__global__ void __launch_bounds__(256) k_prep_x(const float* __restrict__ x) {
    __shared__ float tile[32][33];
    const int bc = blockIdx.z;
    const int n10 = blockIdx.x * 32, n20 = blockIdx.y * 32;
    const float* X = x + (size_t)bc * (HH*HH);
    #pragma unroll
    for (int r = 0; r < 4; r++) {
        int n1 = n10 + threadIdx.y + r*8;
        tile[threadIdx.y + r*8][threadIdx.x] = X[(size_t)n1 * HH + n20 + threadIdx.x];
    }
    __syncthreads();
    const size_t ob = (size_t)bc * (HH*HH);
    #pragma unroll
    for (int r = 0; r < 4; r++) {
        int n2 = n20 + threadIdx.y + r*8;
        split_store(g_xTh, g_xTl, ob + (size_t)n2 * HH + n10 + threadIdx.x,
                    tile[threadIdx.x][threadIdx.y + r*8]);
    }
}

// ---------------------------------------------------------------------------
// fwd_cols via mma: C[512, 256] = A[512, 768]*B[256, 768]^T per bc batch.
// A rows 0..255 -> T1r, 256..511 -> T1i. K-blocks: {(A1h,xTh),(A1l,xTh),(A1h,xTl)}.
// Epilogue: split-bf16 T1. grid (2 ntile, 4 mtile, 16 batch), 256 threads.
__global__ void __launch_bounds__(256) k_fwd_cols_mma() {
    extern __shared__ char dyn_smem[];
    char* base = (char*)(((uintptr_t)dyn_smem + 127) & ~(uintptr_t)127);
    const uint32_t tiles = smem_u32(base);

    const int t = threadIdx.x, lane = t & 31, wid = t >> 5;
    const int wm = wid >> 2, wn = wid & 3;
    const int ntile = blockIdx.x, mtile = blockIdx.y, batch = blockIdx.z;

    const size_t xB = (size_t)batch * (HH * HH);
    const __nv_bfloat16* Ablk[3] = { g_A1h, g_A1l, g_A1h };
    const __nv_bfloat16* Bblk[3] = { g_xTh + xB, g_xTh + xB, g_xTl + xB };

    const int grow = t >> 1, ghalf = t & 1;
    const size_t aGbase = (size_t)(mtile*128 + grow) * HH + ghalf*32;
    const size_t bGbase = (size_t)(ntile*128 + grow) * HH + ghalf*32;
    const uint32_t sOff = (uint32_t)(grow * ROWB + ghalf * 64);
    const uint32_t aFrag = (uint32_t)((wm*64 + (lane & 15)) * ROWB + (lane >> 4) * 16);
    const uint32_t bFrag = (uint32_t)((wn*32 + (lane & 7)) * ROWB + ((lane >> 3) & 1) * 16);

    float acc[4][4][4];
    #pragma unroll
    for (int i = 0; i < 4; i++)
        #pragma unroll
        for (int j = 0; j < 4; j++)
            #pragma unroll
            for (int q = 0; q < 4; q++) acc[i][j][q] = 0.f;

    uint4 av[4], bv[4];
    {
        const __nv_bfloat16* Ag = Ablk[0] + aGbase;
        const __nv_bfloat16* Bg = Bblk[0] + bGbase;
        #pragma unroll
        for (int i = 0; i < 4; i++) {
            av[i] = *(const uint4*)(Ag + i*8);
            bv[i] = *(const uint4*)(Bg + i*8);
        }
    }

    for (int c = 0; c < 12; c++) {
        const int buf = c & 1;
        char* aT = base + buf * BUFB;
        char* bT = aT + TILEB;
        __syncthreads();
        #pragma unroll
        for (int i = 0; i < 4; i++) {
            *(uint4*)(aT + sOff + i*16) = av[i];
            *(uint4*)(bT + sOff + i*16) = bv[i];
        }
        __syncthreads();
        if (c + 1 < 12) {
            const int blk = (c + 1) >> 2;
            const int k0  = ((c + 1) & 3) * KC;
            const __nv_bfloat16* Ag = Ablk[blk] + aGbase + k0;
            const __nv_bfloat16* Bg = Bblk[blk] + bGbase + k0;
            #pragma unroll
            for (int i = 0; i < 4; i++) {
                av[i] = *(const uint4*)(Ag + i*8);
                bv[i] = *(const uint4*)(Bg + i*8);
            }
        }
        const uint32_t aBase = tiles + buf * BUFB + aFrag;
        const uint32_t bBase = tiles + buf * BUFB + TILEB + bFrag;
        #pragma unroll
        for (int kk = 0; kk < 4; kk++) {
            uint32_t af[4][4], bf[4][2];
            #pragma unroll
            for (int mi = 0; mi < 4; mi++)
                ldsm_x4(af[mi][0], af[mi][1], af[mi][2], af[mi][3],
                        aBase + mi * (16 * ROWB) + kk * 32);
            #pragma unroll
            for (int ni = 0; ni < 4; ni++)
                ldsm_x2(bf[ni][0], bf[ni][1], bBase + ni * (8 * ROWB) + kk * 32);
            #pragma unroll
            for (int mi = 0; mi < 4; mi++)
                #pragma unroll
                for (int ni = 0; ni < 4; ni++)
                    mma_bf16(acc[mi][ni], af[mi], bf[ni]);
        }
    }

    // epilogue: split-bf16 T1 (rows<256 -> T1r, else T1i)
    const int group = lane >> 2, tid4 = lane & 3;
    const bool isR = (mtile < 2);
    __nv_bfloat16* Th = (isR ? g_T1rh : g_T1ih) + xB;
    __nv_bfloat16* Tl = (isR ? g_T1rl : g_T1il) + xB;
    const int colBase = ntile*128 + wn*32 + tid4*2;
    const int rowBase = (mtile & 1)*128 + wm*64 + group;
    #pragma unroll
    for (int mi = 0; mi < 4; mi++) {
        #pragma unroll
        for (int ni = 0; ni < 4; ni++) {
            int m = rowBase + mi*16;
            int cn = colBase + ni*8;
            split_store(Th, Tl, (size_t)m * HH + cn,           acc[mi][ni][0]);
            split_store(Th, Tl, (size_t)m * HH + cn + 1,       acc[mi][ni][1]);
            split_store(Th, Tl, (size_t)(m + 8) * HH + cn,     acc[mi][ni][2]);
            split_store(Th, Tl, (size_t)(m + 8) * HH + cn + 1, acc[mi][ni][3]);
        }
    }
}

// ---------------------------------------------------------------------------
// fwd_rows via mma: C[256, 1024] = A[256, 1536]*B[1024, 1536]^T per bc batch.
// grid (8 ntile, 2 mtile, 16 batch), 256 threads.
__global__ void __launch_bounds__(256) k_fwd_rows_mma() {
    extern __shared__ char dyn_smem[];
    char* base = (char*)(((uintptr_t)dyn_smem + 127) & ~(uintptr_t)127);
    const uint32_t tiles = smem_u32(base);

    const int t = threadIdx.x, lane = t & 31, wid = t >> 5;
    const int wm = wid >> 2, wn = wid & 3;
    const int ntile = blockIdx.x, mtile = blockIdx.y, batch = blockIdx.z;

    const size_t aB = (size_t)batch * (HH * HH);
    const __nv_bfloat16* Ablk[6] = { g_T1rh + aB, g_T1ih + aB, g_T1rl + aB,
                                     g_T1il + aB, g_T1rh + aB, g_T1ih + aB };
    const __nv_bfloat16* Bblk[6] = { g_Ph, g_Qh, g_Ph, g_Qh, g_Pl, g_Ql };

    const int grow = t >> 1, ghalf = t & 1;
    const size_t aGbase = (size_t)(mtile*128 + grow) * HH + ghalf*32;
    const size_t bGbase = (size_t)(ntile*128 + grow) * HH + ghalf*32;
    const uint32_t sOff = (uint32_t)(grow * ROWB + ghalf * 64);
    const uint32_t aFrag = (uint32_t)((wm*64 + (lane & 15)) * ROWB + (lane >> 4) * 16);
    const uint32_t bFrag = (uint32_t)((wn*32 + (lane & 7)) * ROWB + ((lane >> 3) & 1) * 16);

    float acc[4][4][4];
    #pragma unroll
    for (int i = 0; i < 4; i++)
        #pragma unroll
        for (int j = 0; j < 4; j++)
            #pragma unroll
            for (int q = 0; q < 4; q++) acc[i][j][q] = 0.f;

    uint4 av[4], bv[4];
    {
        const __nv_bfloat16* Ag = Ablk[0] + aGbase;
        const __nv_bfloat16* Bg = Bblk[0] + bGbase;
        #pragma unroll
        for (int i = 0; i < 4; i++) {
            av[i] = *(const uint4*)(Ag + i*8);
            bv[i] = *(const uint4*)(Bg + i*8);
        }
    }

    for (int c = 0; c < 24; c++) {
        const int buf = c & 1;
        char* aT = base + buf * BUFB;
        char* bT = aT + TILEB;
        __syncthreads();
        #pragma unroll
        for (int i = 0; i < 4; i++) {
            *(uint4*)(aT + sOff + i*16) = av[i];
            *(uint4*)(bT + sOff + i*16) = bv[i];
        }
        __syncthreads();
        if (c + 1 < 24) {
            const int blk = (c + 1) >> 2;
            const int k0  = ((c + 1) & 3) * KC;
            const __nv_bfloat16* Ag = Ablk[blk] + aGbase + k0;
            const __nv_bfloat16* Bg = Bblk[blk] + bGbase + k0;
            #pragma unroll
            for (int i = 0; i < 4; i++) {
                av[i] = *(const uint4*)(Ag + i*8);
                bv[i] = *(const uint4*)(Bg + i*8);
            }
        }
        const uint32_t aBase = tiles + buf * BUFB + aFrag;
        const uint32_t bBase = tiles + buf * BUFB + TILEB + bFrag;
        #pragma unroll
        for (int kk = 0; kk < 4; kk++) {
            uint32_t af[4][4], bf[4][2];
            #pragma unroll
            for (int mi = 0; mi < 4; mi++)
                ldsm_x4(af[mi][0], af[mi][1], af[mi][2], af[mi][3],
                        aBase + mi * (16 * ROWB) + kk * 32);
            #pragma unroll
            for (int ni = 0; ni < 4; ni++)
                ldsm_x2(bf[ni][0], bf[ni][1], bBase + ni * (8 * ROWB) + kk * 32);
            #pragma unroll
            for (int mi = 0; mi < 4; mi++)
                #pragma unroll
                for (int ni = 0; ni < 4; ni++)
                    mma_bf16(acc[mi][ni], af[mi], bf[ni]);
        }
    }

    const int group = lane >> 2, tid4 = lane & 3;
    float* F = ((ntile < 4) ? g_Fr : g_Fi) + (size_t)batch * (HH*LD);
    const int colBase = (ntile & 3) * 128 + wn*32 + tid4*2;
    const int rowBase = mtile*128 + wm*64 + group;
    #pragma unroll
    for (int mi = 0; mi < 4; mi++) {
        #pragma unroll
        for (int ni = 0; ni < 4; ni++) {
            int m = rowBase + mi*16;
            int cn = colBase + ni*8;
            *(float2*)&F[(size_t)m * LD + cn]       = make_float2(acc[mi][ni][0], acc[mi][ni][1]);
            *(float2*)&F[(size_t)(m + 8) * LD + cn] = make_float2(acc[mi][ni][2], acc[mi][ni][3]);
        }
    }
}

// ---------------------------------------------------------------------------
// Einsum with Hermitian weight projection; outputs split-bf16 H.
__global__ void __launch_bounds__(256) k_einsum_h(const float* __restrict__ w) {
    int k2 = blockIdx.x * 256 + threadIdx.x;       // 0..511
    int k1 = blockIdx.y;                           // 0..255
    if (k2 == 511) {
        #pragma unroll
        for (int bo = 0; bo < 32; bo++) {
            int idx = bo * (HH*LD) + k1 * LD + 511;
            g_Hrh[idx] = __float2bfloat16(0.f); g_Hrl[idx] = __float2bfloat16(0.f);
            g_Hih[idx] = __float2bfloat16(0.f); g_Hil[idx] = __float2bfloat16(0.f);
        }
        return;
    }
    float fr[16], fi[16];
    {
        int off = k1 * LD + k2;
        #pragma unroll
        for (int bc = 0; bc < 16; bc++) {
            fr[bc] = g_Fr[bc * (HH*LD) + off];
            fi[bc] = g_Fi[bc * (HH*LD) + off];
        }
    }
    const int m1 = (k1 == 0) ? 0 : (NF - k1);
    const int m2 = (k2 == 0) ? 0 : (NF - k2);
    const int wbase  = (k1 * NF + k2) * 2;
    const int wmbase = (m1 * NF + m2) * 2;
    const float s = (k1 == 0) ? 0.5f : 1.0f;
    const int hidx = k1 * LD + k2;
    #pragma unroll
    for (int o = 0; o < 8; o++) {
        float whr[4], whi[4];
        #pragma unroll
        for (int cc = 0; cc < 4; cc++) {
            int base  = (o * 4 + cc) * (NN2 * 2);
            float w1r = w[base + wbase],  w1i = w[base + wbase + 1];
            float w2r = w[base + wmbase], w2i = w[base + wmbase + 1];
            whr[cc] = s * (w1r + w2r);
            whi[cc] = s * (w1i - w2i);
        }
        #pragma unroll
        for (int b = 0; b < 4; b++) {
            float ar = 0.f, ai = 0.f;
            #pragma unroll
            for (int cc = 0; cc < 4; cc++) {
                float xr = fr[b*4+cc], xi = fi[b*4+cc];
                ar += xr * whr[cc] - xi * whi[cc];
                ai += xr * whi[cc] + xi * whr[cc];
            }
            int idx = (b * 8 + o) * (HH*LD) + hidx;
            split_store(g_Hrh, g_Hrl, idx, ar);
            split_store(g_Hih, g_Hil, idx, ai);
        }
    }
}

// ---------------------------------------------------------------------------
// inv_u via mma: C[256, 512] = A[256, 3072]*B[512, 3072]^T per bo batch.
// Epilogue writes TRANSPOSED split-bf16 U. grid (4, 2, 32), 256 threads.
__global__ void __launch_bounds__(256) k_inv_u_mma() {
    extern __shared__ char dyn_smem[];
    char* base = (char*)(((uintptr_t)dyn_smem + 127) & ~(uintptr_t)127);
    const uint32_t tiles = smem_u32(base);

    const int t = threadIdx.x, lane = t & 31, wid = t >> 5;
    const int wm = wid >> 2, wn = wid & 3;
    const int ntile = blockIdx.x, mtile = blockIdx.y, batch = blockIdx.z;

    const size_t hB = (size_t)batch * (HH * LD);
    const __nv_bfloat16* Ablk[6] = { g_Hrh + hB, g_Hih + hB, g_Hrl + hB,
                                     g_Hil + hB, g_Hrh + hB, g_Hih + hB };
    const __nv_bfloat16* Bblk[6] = { g_Brh, g_Bih, g_Brh, g_Bih, g_Brl, g_Bil };

    const int grow = t >> 1, ghalf = t & 1;
    const size_t aGbase = (size_t)(mtile*128 + grow) * LD + ghalf*32;
    const size_t bGbase = (size_t)(ntile*128 + grow) * LD + ghalf*32;
    const uint32_t sOff = (uint32_t)(grow * ROWB + ghalf * 64);
    const uint32_t aFrag = (uint32_t)((wm*64 + (lane & 15)) * ROWB + (lane >> 4) * 16);
    const uint32_t bFrag = (uint32_t)((wn*32 + (lane & 7)) * ROWB + ((lane >> 3) & 1) * 16);

    float acc[4][4][4];
    #pragma unroll
    for (int i = 0; i < 4; i++)
        #pragma unroll
        for (int j = 0; j < 4; j++)
            #pragma unroll
            for (int q = 0; q < 4; q++) acc[i][j][q] = 0.f;

    uint4 av[4], bv[4];
    {
        const __nv_bfloat16* Ag = Ablk[0] + aGbase;
        const __nv_bfloat16* Bg = Bblk[0] + bGbase;
        #pragma unroll
        for (int i = 0; i < 4; i++) {
            av[i] = *(const uint4*)(Ag + i*8);
            bv[i] = *(const uint4*)(Bg + i*8);
        }
    }

    for (int c = 0; c < 48; c++) {
        const int buf = c & 1;
        char* aT = base + buf * BUFB;
        char* bT = aT + TILEB;
        __syncthreads();
        #pragma unroll
        for (int i = 0; i < 4; i++) {
            *(uint4*)(aT + sOff + i*16) = av[i];
            *(uint4*)(bT + sOff + i*16) = bv[i];
        }
        __syncthreads();
        if (c + 1 < 48) {
            const int blk = (c + 1) >> 3;
            const int k0  = ((c + 1) & 7) * KC;
            const __nv_bfloat16* Ag = Ablk[blk] + aGbase + k0;
            const __nv_bfloat16* Bg = Bblk[blk] + bGbase + k0;
            #pragma unroll
            for (int i = 0; i < 4; i++) {
                av[i] = *(const uint4*)(Ag + i*8);
                bv[i] = *(const uint4*)(Bg + i*8);
            }
        }
        const uint32_t aBase = tiles + buf * BUFB + aFrag;
        const uint32_t bBase = tiles + buf * BUFB + TILEB + bFrag;
        #pragma unroll
        for (int kk = 0; kk < 4; kk++) {
            uint32_t af[4][4], bf[4][2];
            #pragma unroll
            for (int mi = 0; mi < 4; mi++)
                ldsm_x4(af[mi][0], af[mi][1], af[mi][2], af[mi][3],
                        aBase + mi * (16 * ROWB) + kk * 32);
            #pragma unroll
            for (int ni = 0; ni < 4; ni++)
                ldsm_x2(bf[ni][0], bf[ni][1], bBase + ni * (8 * ROWB) + kk * 32);
            #pragma unroll
            for (int mi = 0; mi < 4; mi++)
                #pragma unroll
                for (int ni = 0; ni < 4; ni++)
                    mma_bf16(acc[mi][ni], af[mi], bf[ni]);
        }
    }

    const int group = lane >> 2, tid4 = lane & 3;
    const bool isR = (ntile < 2);
    __nv_bfloat16* Th = (isR ? g_UrTh : g_UiTh) + (size_t)batch * (HH*HH);
    __nv_bfloat16* Tl = (isR ? g_UrTl : g_UiTl) + (size_t)batch * (HH*HH);
    const int colBase = (ntile & 1) * 128 + wn*32 + tid4*2;
    const int rowBase = mtile*128 + wm*64 + group;
    #pragma unroll
    for (int mi = 0; mi < 4; mi++) {
        #pragma unroll
        for (int ni = 0; ni < 4; ni++) {
            int m = rowBase + mi*16;
            int cn = colBase + ni*8;
            split_store(Th, Tl, (size_t)cn * HH + m,           acc[mi][ni][0]);
            split_store(Th, Tl, (size_t)(cn + 1) * HH + m,     acc[mi][ni][1]);
            split_store(Th, Tl, (size_t)cn * HH + m + 8,       acc[mi][ni][2]);
            split_store(Th, Tl, (size_t)(cn + 1) * HH + m + 8, acc[mi][ni][3]);
        }
    }
}

// ---------------------------------------------------------------------------
// k_out via mma: out = scale * (A[256,1536]*B[256,1536]^T) + bias.
// grid (2 ntile, 2 mtile, 32 batch), 256 threads.
__global__ void __launch_bounds__(256) k_out_mma(const float* __restrict__ bias,
                                                 float* __restrict__ out) {
    extern __shared__ char dyn_smem[];
    char* base = (char*)(((uintptr_t)dyn_smem + 127) & ~(uintptr_t)127);
    const uint32_t tiles = smem_u32(base);

    const int t = threadIdx.x, lane = t & 31, wid = t >> 5;
    const int wm = wid >> 2, wn = wid & 3;
    const int ntile = blockIdx.x, mtile = blockIdx.y, batch = blockIdx.z;
    const float scale = 1.0f / ((float)NF * (float)NF);
    const float bias_v = bias[batch & 7];

    const size_t uB = (size_t)batch * (HH * HH);
    const __nv_bfloat16* Ablk[6] = { g_sTrh, g_sTih, g_sTrl, g_sTil, g_sTrh, g_sTih };
    const __nv_bfloat16* Bblk[6] = { g_UrTh + uB, g_UiTh + uB, g_UrTh + uB,
                                     g_UiTh + uB, g_UrTl + uB, g_UiTl + uB };

    const int grow = t >> 1, ghalf = t & 1;
    const size_t aGbase = (size_t)(CROP0 + mtile*128 + grow) * HH + ghalf*32;
    const size_t bGbase = (size_t)(ntile*128 + grow) * HH + ghalf*32;
    const uint32_t sOff = (uint32_t)(grow * ROWB + ghalf * 64);
    const uint32_t aFrag = (uint32_t)((wm*64 + (lane & 15)) * ROWB + (lane >> 4) * 16);
    const uint32_t bFrag = (uint32_t)((wn*32 + (lane & 7)) * ROWB + ((lane >> 3) & 1) * 16);

    float acc[4][4][4];
    #pragma unroll
    for (int i = 0; i < 4; i++)
        #pragma unroll
        for (int j = 0; j < 4; j++)
            #pragma unroll
            for (int q = 0; q < 4; q++) acc[i][j][q] = 0.f;

    uint4 av[4], bv[4];
    {
        const __nv_bfloat16* Ag = Ablk[0] + aGbase;
        const __nv_bfloat16* Bg = Bblk[0] + bGbase;
        #pragma unroll
        for (int i = 0; i < 4; i++) {
            av[i] = *(const uint4*)(Ag + i*8);
            bv[i] = *(const uint4*)(Bg + i*8);
        }
    }

    for (int c = 0; c < 24; c++) {
        const int buf = c & 1;
        char* aT = base + buf * BUFB;
        char* bT = aT + TILEB;
        __syncthreads();
        #pragma unroll
        for (int i = 0; i < 4; i++) {
            *(uint4*)(aT + sOff + i*16) = av[i];
            *(uint4*)(bT + sOff + i*16) = bv[i];
        }
        __syncthreads();
        if (c + 1 < 24) {
            const int blk = (c + 1) >> 2;
            const int k0  = ((c + 1) & 3) * KC;
            const __nv_bfloat16* Ag = Ablk[blk] + aGbase + k0;
            const __nv_bfloat16* Bg = Bblk[blk] + bGbase + k0;
            #pragma unroll
            for (int i = 0; i < 4; i++) {
                av[i] = *(const uint4*)(Ag + i*8);
                bv[i] = *(const uint4*)(Bg + i*8);
            }
        }
        const uint32_t aBase = tiles + buf * BUFB + aFrag;
        const uint32_t bBase = tiles + buf * BUFB + TILEB + bFrag;
        #pragma unroll
        for (int kk = 0; kk < 4; kk++) {
            uint32_t af[4][4], bf[4][2];
            #pragma unroll
            for (int mi = 0; mi < 4; mi++)
                ldsm_x4(af[mi][0], af[mi][1], af[mi][2], af[mi][3],
                        aBase + mi * (16 * ROWB) + kk * 32);
            #pragma unroll
            for (int ni = 0; ni < 4; ni++)
                ldsm_x2(bf[ni][0], bf[ni][1], bBase + ni * (8 * ROWB) + kk * 32);
            #pragma unroll
            for (int mi = 0; mi < 4; mi++)
                #pragma unroll
                for (int ni = 0; ni < 4; ni++)
                    mma_bf16(acc[mi][ni], af[mi], bf[ni]);
        }
    }

    const int group = lane >> 2, tid4 = lane & 3;
    float* C = out + (size_t)batch * (HH*HH);
    const int colBase = ntile*128 + wn*32 + tid4*2;
    const int rowBase = mtile*128 + wm*64 + group;
    #pragma unroll
    for (int mi = 0; mi < 4; mi++) {
        #pragma unroll
        for (int ni = 0; ni < 4; ni++) {
            int m = rowBase + mi*16;
            int cn = colBase + ni*8;
            *(float2*)&C[(size_t)m * HH + cn] =
                make_float2(acc[mi][ni][0]*scale + bias_v, acc[mi][ni][1]*scale + bias_v);
            *(float2*)&C[(size_t)(m + 8) * HH + cn] =
                make_float2(acc[mi][ni][2]*scale + bias_v, acc[mi][ni][3]*scale + bias_v);
        }
    }
}

// ---------------------------------------------------------------------------
extern "C" void kernel_launch(void* const* d_in, const int* in_sizes, int n_in,
                              void* d_out, int out_size) {
    const float* im   = (const float*)d_in[0];   // (4,4,256,256)
    const float* wgt  = (const float*)d_in[1];   // (8,4,511,511,2)
    const float* bias = (const float*)d_in[2];   // (8,1,1)
    float* out = (float*)d_out;                  // (4,8,256,256)

    static int smem_set = 0;
    if (!smem_set) {
        cudaFuncSetAttribute(k_fwd_cols_mma, cudaFuncAttributeMaxDynamicSharedMemorySize, MMA_SMEM);
        cudaFuncSetAttribute(k_fwd_rows_mma, cudaFuncAttributeMaxDynamicSharedMemorySize, MMA_SMEM);
        cudaFuncSetAttribute(k_inv_u_mma,    cudaFuncAttributeMaxDynamicSharedMemorySize, MMA_SMEM);
        cudaFuncSetAttribute(k_out_mma,      cudaFuncAttributeMaxDynamicSharedMemorySize, MMA_SMEM);
        smem_set = 1;
    }

    k_twiddle     <<<(LD * LD) / 256, 256>>>();
    k_prep_binv   <<<(LD * LD) / 256, 256>>>();
    k_prep_pq     <<<(1024 * HH) / 256, 256>>>();
    k_prep_x      <<<dim3(8, 8, 16), dim3(32, 8)>>>(im);
    k_fwd_cols_mma<<<dim3(2, 4, 16), 256, MMA_SMEM>>>();
    k_fwd_rows_mma<<<dim3(8, 2, 16), 256, MMA_SMEM>>>();
    k_einsum_h    <<<dim3(2, 256),   256>>>(wgt);
    k_inv_u_mma   <<<dim3(4, 2, 32), 256, MMA_SMEM>>>();
    k_out_mma     <<<dim3(2, 2, 32), 256, MMA_SMEM>>>(bias, out);
}